// round 1
// baseline (speedup 1.0000x reference)
#include <cuda_runtime.h>
#include <math.h>

#define D_MODEL   256
#define D_STATE   64
#define D_CONV    4
#define HEADDIM   64
#define D_INNER   512
#define NHEADS    8
#define CONV_CH   640      // D_INNER + 2*D_STATE
#define D_IN_PROJ 1160     // 2*D_INNER + 2*D_STATE + NHEADS
#define SEQ       64
#define NSEQ      512      // sequences per direction (8*64)
#define NTOK      32768    // total tokens (8*64*64)

// ---------------- scratch (static device memory; allocation-free) ----------------
__device__ float g_Z[(size_t)NTOK * D_IN_PROJ];   // 152 MB, reused per direction
__device__ float g_Yh[(size_t)NTOK * D_INNER];    // 64 MB
__device__ float g_Yv[(size_t)NTOK * D_INNER];    // 64 MB
__device__ float g_Wt[D_MODEL * D_IN_PROJ];       // transposed in_w  [K=256][N=1160]
__device__ float g_WcT[2 * D_INNER * D_MODEL];    // combined out proj [d][k=512][n=256]

// ---------------- transpose in_w (1160,256) -> (256,1160) ----------------
__global__ void transpose_inw(const float* __restrict__ w) {
    int idx = blockIdx.x * 256 + threadIdx.x;
    if (idx < D_IN_PROJ * D_MODEL) {
        int n = idx >> 8;      // /256
        int k = idx & 255;
        g_Wt[k * D_IN_PROJ + n] = w[idx];
    }
}

// ---------------- generic fp32 SGEMM: C[M][N] = A[M][K] * B[K][N] (+bias)(+=) ----
// M = 32768 fixed multiple of 128. Tile 128x128x8, 256 threads, 8x8 micro-tile.
__global__ void __launch_bounds__(256) sgemm(
    const float* __restrict__ A, const float* __restrict__ B,
    float* __restrict__ C, int K, int N,
    const float* __restrict__ bias, int accumulate)
{
    __shared__ float As[8][128];
    __shared__ float Bs[8][128];
    const int tid = threadIdx.x;
    const int m0 = blockIdx.x * 128;
    const int n0 = blockIdx.y * 128;

    const int arow = tid >> 1;          // 0..127
    const int akc  = (tid & 1) * 4;     // 0 or 4
    const int brow = tid >> 5;          // 0..7
    const int bcol = (tid & 31) * 4;    // 0..124

    const float* Ap = A + (size_t)(m0 + arow) * K + akc;
    const float* Bp = B + (size_t)brow * N + n0 + bcol;
    const bool bfull = (n0 + bcol + 3 < N);

    float acc[8][8];
#pragma unroll
    for (int i = 0; i < 8; i++)
#pragma unroll
        for (int j = 0; j < 8; j++) acc[i][j] = 0.f;

    const int tm = (tid >> 4) * 8;
    const int tn = (tid & 15) * 8;

    for (int k0 = 0; k0 < K; k0 += 8) {
        float4 av = *(const float4*)(Ap);
        Ap += 8;
        float4 bv;
        if (bfull) {
            bv = *(const float4*)(Bp);
        } else {
            int n = n0 + bcol;
            bv.x = (n + 0 < N) ? Bp[0] : 0.f;
            bv.y = (n + 1 < N) ? Bp[1] : 0.f;
            bv.z = (n + 2 < N) ? Bp[2] : 0.f;
            bv.w = (n + 3 < N) ? Bp[3] : 0.f;
        }
        Bp += (size_t)8 * N;

        As[akc + 0][arow] = av.x;
        As[akc + 1][arow] = av.y;
        As[akc + 2][arow] = av.z;
        As[akc + 3][arow] = av.w;
        *(float4*)&Bs[brow][bcol] = bv;
        __syncthreads();

#pragma unroll
        for (int kk = 0; kk < 8; kk++) {
            float4 a0 = *(const float4*)&As[kk][tm];
            float4 a1 = *(const float4*)&As[kk][tm + 4];
            float4 b0 = *(const float4*)&Bs[kk][tn];
            float4 b1 = *(const float4*)&Bs[kk][tn + 4];
            float a[8] = {a0.x, a0.y, a0.z, a0.w, a1.x, a1.y, a1.z, a1.w};
            float b[8] = {b0.x, b0.y, b0.z, b0.w, b1.x, b1.y, b1.z, b1.w};
#pragma unroll
            for (int i = 0; i < 8; i++)
#pragma unroll
                for (int j = 0; j < 8; j++)
                    acc[i][j] = fmaf(a[i], b[j], acc[i][j]);
        }
        __syncthreads();
    }

#pragma unroll
    for (int i = 0; i < 8; i++) {
        int m = m0 + tm + i;
#pragma unroll
        for (int j = 0; j < 8; j++) {
            int n = n0 + tn + j;
            if (n < N) {
                float v = acc[i][j];
                if (bias) v += bias[n];
                float* cp = &C[(size_t)m * N + n];
                if (accumulate) v += *cp;
                *cp = v;
            }
        }
    }
}

// ---------------- fused conv + SiLU + softplus + SSM scan + gate + RMSnorm ------
// One block per sequence (512 threads = 512 y-channels = 8 heads x 64 p).
// State h[p][n] lives in registers: 64 floats per thread.
__global__ void __launch_bounds__(512, 1) scan_kernel(
    const float* __restrict__ conv_w, const float* __restrict__ conv_b,
    const float* __restrict__ dt_bias, const float* __restrict__ A_log,
    const float* __restrict__ Dv, const float* __restrict__ norm_w,
    float* __restrict__ Yout, int vertical)
{
    const int tid  = threadIdx.x;
    const int head = tid >> 6;
    const int s    = blockIdx.x;

    int base, stride;
    if (vertical) { int b = s >> 6, w = s & 63; base = b * 4096 + w; stride = 64; }
    else          { base = s * 64; stride = 1; }

    __shared__ __align__(16) float ring[4][CONV_CH];
    __shared__ __align__(16) float Bsh[64];
    __shared__ __align__(16) float Csh[64];
    __shared__ float dt_s[8], dA_s[8], Aneg_s[8], dtb_s[8];
    __shared__ float red[16];
    __shared__ float s_inv;

    for (int i = tid; i < 4 * CONV_CH; i += 512) (&ring[0][0])[i] = 0.f;
    if (tid < 8) { Aneg_s[tid] = -expf(A_log[tid]); dtb_s[tid] = dt_bias[tid]; }

    const float w0 = conv_w[tid * 4 + 0], w1 = conv_w[tid * 4 + 1];
    const float w2 = conv_w[tid * 4 + 2], w3 = conv_w[tid * 4 + 3];
    const float cb = conv_b[tid];
    float u0 = 0.f, u1 = 0.f, u2 = 0.f, u3 = 0.f, cb2 = 0.f;
    const int c2 = 512 + tid;
    if (tid < 128) {
        u0 = conv_w[c2 * 4 + 0]; u1 = conv_w[c2 * 4 + 1];
        u2 = conv_w[c2 * 4 + 2]; u3 = conv_w[c2 * 4 + 3];
        cb2 = conv_b[c2];
    }
    const float Dh = Dv[head];
    const float nw = norm_w[tid];

    float h[64];
#pragma unroll
    for (int n = 0; n < 64; n++) h[n] = 0.f;

    __syncthreads();

    for (int t = 0; t < SEQ; t++) {
        const int r = base + t * stride;
        const float* row = g_Z + (size_t)r * D_IN_PROJ;
        const int slot = t & 3;
        // stage raw xBC row into ring buffer; z loaded directly
        ring[slot][tid] = row[512 + tid];
        if (tid < 128) ring[slot][512 + tid] = row[1024 + tid];
        const float z = row[tid];
        if (tid < 8) {
            float draw = row[1152 + tid] + dtb_s[tid];
            float dt = (draw > 20.f) ? draw : log1pf(expf(draw));
            dt_s[tid] = dt;
            dA_s[tid] = expf(dt * Aneg_s[tid]);
        }
        __syncthreads();

        // depthwise causal conv width-4 + SiLU (rows <0 are zeros in ring)
        const int s0 = (t + 1) & 3, s1 = (t + 2) & 3, s2 = (t + 3) & 3, s3 = slot;
        float xv = cb;
        xv = fmaf(ring[s0][tid], w0, xv);
        xv = fmaf(ring[s1][tid], w1, xv);
        xv = fmaf(ring[s2][tid], w2, xv);
        xv = fmaf(ring[s3][tid], w3, xv);
        xv = xv / (1.f + expf(-xv));
        if (tid < 128) {
            float v = cb2;
            v = fmaf(ring[s0][c2], u0, v);
            v = fmaf(ring[s1][c2], u1, v);
            v = fmaf(ring[s2][c2], u2, v);
            v = fmaf(ring[s3][c2], u3, v);
            v = v / (1.f + expf(-v));
            if (tid < 64) Bsh[tid] = v; else Csh[tid - 64] = v;
        }
        __syncthreads();

        // SSM scan step: h = h*dA + (dt*x)*B ; y = <h, C>
        const float dA  = dA_s[head];
        const float dtx = dt_s[head] * xv;
        float y = 0.f;
#pragma unroll
        for (int n = 0; n < 64; n += 4) {
            float4 bv = *(const float4*)&Bsh[n];
            float4 cv = *(const float4*)&Csh[n];
            h[n + 0] = fmaf(h[n + 0], dA, dtx * bv.x); y = fmaf(h[n + 0], cv.x, y);
            h[n + 1] = fmaf(h[n + 1], dA, dtx * bv.y); y = fmaf(h[n + 1], cv.y, y);
            h[n + 2] = fmaf(h[n + 2], dA, dtx * bv.z); y = fmaf(h[n + 2], cv.z, y);
            h[n + 3] = fmaf(h[n + 3], dA, dtx * bv.w); y = fmaf(h[n + 3], cv.w, y);
        }
        y = fmaf(xv, Dh, y);

        // gate by silu(z), RMS-norm over the 512 channels of this block
        float g = y * (z / (1.f + expf(-z)));
        float ss = g * g;
#pragma unroll
        for (int o = 16; o; o >>= 1) ss += __shfl_xor_sync(0xffffffffu, ss, o);
        if ((tid & 31) == 0) red[tid >> 5] = ss;
        __syncthreads();
        if (tid < 32) {
            float v = (tid < 16) ? red[tid] : 0.f;
#pragma unroll
            for (int o = 8; o; o >>= 1) v += __shfl_xor_sync(0xffffffffu, v, o);
            if (tid == 0) s_inv = rsqrtf(v * (1.0f / 512.0f) + 1e-5f);
        }
        __syncthreads();
        Yout[(size_t)r * D_INNER + tid] = g * s_inv * nw;
    }
}

// ---------------- fold fc_w into out_w:  WcT[d][k][n] ---------------------------
// WcT[k][n] = sum_j out_w[j][k] * (fc_w[n][fo+j] + fc_w[n][fo+256+j])
__global__ void __launch_bounds__(256) wcomb_kernel(
    const float* __restrict__ mh_out_w, const float* __restrict__ mv_out_w,
    const float* __restrict__ fc_w)
{
    const int d  = blockIdx.x;              // 0 = v, 1 = h
    const int k0 = blockIdx.y * 64;
    const int nb = blockIdx.z * 64;
    const float* ow = d ? mh_out_w : mv_out_w;
    const int fo = d ? 512 : 0;
    __shared__ float ows[128][64];
    const int kk = threadIdx.x & 63;
    const int n  = nb + (threadIdx.x >> 6) * 16;
    float acc[16];
#pragma unroll
    for (int i = 0; i < 16; i++) acc[i] = 0.f;

    for (int jo = 0; jo < 256; jo += 128) {
        for (int i = threadIdx.x; i < 128 * 64; i += 256) {
            int j = i >> 6, c = i & 63;
            ows[j][c] = ow[(size_t)(jo + j) * 512 + k0 + c];
        }
        __syncthreads();
        for (int j = 0; j < 128; j++) {
            float o = ows[j][kk];
            int jj = jo + j;
#pragma unroll 4
            for (int i = 0; i < 16; i++) {
                float f = fc_w[(n + i) * 1024 + fo + jj] +
                          fc_w[(n + i) * 1024 + fo + 256 + jj];
                acc[i] = fmaf(o, f, acc[i]);
            }
        }
        __syncthreads();
    }
#pragma unroll
    for (int i = 0; i < 16; i++)
        g_WcT[(size_t)d * D_INNER * D_MODEL + (size_t)(k0 + kk) * 256 + (n + i)] = acc[i];
}

// ---------------- launch ----------------
extern "C" void kernel_launch(void* const* d_in, const int* in_sizes, int n_in,
                              void* d_out, int out_size)
{
    (void)in_sizes; (void)n_in; (void)out_size;
    const float* x          = (const float*)d_in[0];
    const float* mh_in_w    = (const float*)d_in[1];
    const float* mh_conv_w  = (const float*)d_in[2];
    const float* mh_conv_b  = (const float*)d_in[3];
    const float* mh_dt_bias = (const float*)d_in[4];
    const float* mh_A_log   = (const float*)d_in[5];
    const float* mh_D       = (const float*)d_in[6];
    const float* mh_norm_w  = (const float*)d_in[7];
    const float* mh_out_w   = (const float*)d_in[8];
    const float* mv_in_w    = (const float*)d_in[9];
    const float* mv_conv_w  = (const float*)d_in[10];
    const float* mv_conv_b  = (const float*)d_in[11];
    const float* mv_dt_bias = (const float*)d_in[12];
    const float* mv_A_log   = (const float*)d_in[13];
    const float* mv_D       = (const float*)d_in[14];
    const float* mv_norm_w  = (const float*)d_in[15];
    const float* mv_out_w   = (const float*)d_in[16];
    const float* fc_w       = (const float*)d_in[17];
    const float* fc_b       = (const float*)d_in[18];
    float* out = (float*)d_out;

    float *Zp, *Yhp, *Yvp, *Wtp, *WcTp;
    cudaGetSymbolAddress((void**)&Zp,  g_Z);
    cudaGetSymbolAddress((void**)&Yhp, g_Yh);
    cudaGetSymbolAddress((void**)&Yvp, g_Yv);
    cudaGetSymbolAddress((void**)&Wtp, g_Wt);
    cudaGetSymbolAddress((void**)&WcTp, g_WcT);

    const int ntr = (D_IN_PROJ * D_MODEL + 255) / 256;
    const dim3 g_in(NTOK / 128, (D_IN_PROJ + 127) / 128);   // (256, 10)
    const dim3 g_fin(NTOK / 128, D_MODEL / 128);            // (256, 2)

    // horizontal direction
    transpose_inw<<<ntr, 256>>>(mh_in_w);
    sgemm<<<g_in, 256>>>(x, Wtp, Zp, D_MODEL, D_IN_PROJ, nullptr, 0);
    scan_kernel<<<NSEQ, 512>>>(mh_conv_w, mh_conv_b, mh_dt_bias, mh_A_log,
                               mh_D, mh_norm_w, Yhp, 0);
    // vertical direction
    transpose_inw<<<ntr, 256>>>(mv_in_w);
    sgemm<<<g_in, 256>>>(x, Wtp, Zp, D_MODEL, D_IN_PROJ, nullptr, 0);
    scan_kernel<<<NSEQ, 512>>>(mv_conv_w, mv_conv_b, mv_dt_bias, mv_A_log,
                               mv_D, mv_norm_w, Yvp, 1);

    // fold fc into out projections, then single fused epilogue GEMM
    wcomb_kernel<<<dim3(2, 8, 4), 256>>>(mh_out_w, mv_out_w, fc_w);
    sgemm<<<g_fin, 256>>>(Yvp, WcTp, out, D_INNER, D_MODEL, fc_b, 0);
    sgemm<<<g_fin, 256>>>(Yhp, WcTp + D_INNER * D_MODEL, out, D_INNER, D_MODEL,
                          nullptr, 1);
}

// round 3
// speedup vs baseline: 1.4715x; 1.4715x over previous
#include <cuda_runtime.h>
#include <cuda_bf16.h>
#include <math.h>
#include <stdint.h>

#define D_MODEL   256
#define D_INNER   512
#define CONV_CH   640
#define D_IN_PROJ 1160
#define NPAD1     1280     // padded N for in-proj GEMM
#define SEQ       64
#define NSEQ      512
#define NTOK      32768
#define KFIN      1024     // concat K for fused output GEMM

// ---------------- scratch (static device memory; allocation-free) --------------
__device__ float         g_Zh  [(size_t)NTOK * NPAD1];     // in-proj out, horizontal
__device__ float         g_Zv  [(size_t)NTOK * NPAD1];     // in-proj out, vertical
__device__ __nv_bfloat16 g_Xhi [(size_t)NTOK * D_MODEL];
__device__ __nv_bfloat16 g_Xlo [(size_t)NTOK * D_MODEL];
__device__ __nv_bfloat16 g_Whhi[(size_t)NPAD1 * D_MODEL];  // mh in_w bf16 [n][k]
__device__ __nv_bfloat16 g_Whlo[(size_t)NPAD1 * D_MODEL];
__device__ __nv_bfloat16 g_Wvhi[(size_t)NPAD1 * D_MODEL];  // mv in_w bf16 [n][k]
__device__ __nv_bfloat16 g_Wvlo[(size_t)NPAD1 * D_MODEL];
__device__ __nv_bfloat16 g_Yhi [(size_t)NTOK * KFIN];      // [tok][1024] (v|h)
__device__ __nv_bfloat16 g_Ylo [(size_t)NTOK * KFIN];
__device__ __nv_bfloat16 g_WcBhi[(size_t)D_MODEL * KFIN];  // [n=256][k=1024]
__device__ __nv_bfloat16 g_WcBlo[(size_t)D_MODEL * KFIN];

// ---------------- helpers ------------------------------------------------------
__device__ __forceinline__ uint32_t smem_u32(const void* p) {
    uint32_t a;
    asm("{ .reg .u64 t; cvta.to.shared.u64 t, %1; cvt.u32.u64 %0, t; }" : "=r"(a) : "l"(p));
    return a;
}
__device__ __forceinline__ uint32_t swz(uint32_t off) {
    return off ^ ((off >> 3) & 0x70);
}

// ---------------- conversion kernels -------------------------------------------
__global__ void cvt_x_kernel(const float* __restrict__ in) {
    size_t i = (size_t)blockIdx.x * 256 + threadIdx.x;   // float4 index
    float4 v = ((const float4*)in)[i];
    __nv_bfloat16 h0 = __float2bfloat16(v.x), h1 = __float2bfloat16(v.y);
    __nv_bfloat16 h2 = __float2bfloat16(v.z), h3 = __float2bfloat16(v.w);
    __nv_bfloat162 hi01; hi01.x = h0; hi01.y = h1;
    __nv_bfloat162 hi23; hi23.x = h2; hi23.y = h3;
    __nv_bfloat162 lo01, lo23;
    lo01.x = __float2bfloat16(v.x - __bfloat162float(h0));
    lo01.y = __float2bfloat16(v.y - __bfloat162float(h1));
    lo23.x = __float2bfloat16(v.z - __bfloat162float(h2));
    lo23.y = __float2bfloat16(v.w - __bfloat162float(h3));
    ((__nv_bfloat162*)g_Xhi)[2 * i]     = hi01;
    ((__nv_bfloat162*)g_Xhi)[2 * i + 1] = hi23;
    ((__nv_bfloat162*)g_Xlo)[2 * i]     = lo01;
    ((__nv_bfloat162*)g_Xlo)[2 * i + 1] = lo23;
}

__global__ void prep_w_kernel(const float* __restrict__ w,
                              __nv_bfloat16* __restrict__ whi,
                              __nv_bfloat16* __restrict__ wlo) {
    int i = blockIdx.x * 256 + threadIdx.x;    // over NPAD1*256, [n][k] k-contig
    if (i < NPAD1 * D_MODEL) {
        int n = i >> 8;
        float v = (n < D_IN_PROJ) ? w[i] : 0.f;
        __nv_bfloat16 h = __float2bfloat16(v);
        whi[i] = h;
        wlo[i] = __float2bfloat16(v - __bfloat162float(h));
    }
}

// ---------------- mma.sync split-bf16 GEMM --------------------------------------
// C[M][ldc] (fp32) = Ahi*Bhi + Ahi*Blo + Alo*Bhi.
// A: [M][K] k-major bf16; B: [N][K] k-major bf16 (col-major for mma.row.col).
// Tiles 128x128, BK=64, double-buffered cp.async, 8 warps (2x4), warp 64x32.
#define TILE_ELEMS 8192          // 128x64 bf16
#define STAGE_ELEMS 16384        // A tile + B tile
#define GSMEM (2 * STAGE_ELEMS * 2)  // bytes: 65536

__global__ void __launch_bounds__(256, 2) gemm_mma(
    const __nv_bfloat16* __restrict__ A0, const __nv_bfloat16* __restrict__ A1,
    const __nv_bfloat16* __restrict__ B0, const __nv_bfloat16* __restrict__ B1,
    float* __restrict__ C, int K, int ldc, const float* __restrict__ bias)
{
    extern __shared__ __nv_bfloat16 sm[];
    const uint32_t smb = smem_u32(sm);
    const int tid = threadIdx.x, lane = tid & 31, wid = tid >> 5;
    const int m0 = blockIdx.x * 128, n0 = blockIdx.y * 128;
    const int wm = (wid & 1) * 64, wn = (wid >> 1) * 32;
    const int kreg = K >> 6, nk = 3 * kreg;

    // per-thread load coords: row = tid>>1 (0..127), 4 chunks of 16B
    const int lrow = tid >> 1;
    const int lcb  = (tid & 1) * 4;

    // per-thread fragment smem byte offsets (before stage base + swizzle)
    uint32_t arow_b[4], brow_b[4];
#pragma unroll
    for (int mt = 0; mt < 4; mt++)
        arow_b[mt] = (uint32_t)(wm + mt * 16 + (lane & 15)) * 128 + (lane >> 4) * 16;
#pragma unroll
    for (int nt = 0; nt < 4; nt++)
        brow_b[nt] = (uint32_t)(wn + nt * 8 + (lane & 7)) * 128 + ((lane >> 3) & 1) * 16;

    float acc[4][4][4];
#pragma unroll
    for (int a = 0; a < 4; a++)
#pragma unroll
        for (int b = 0; b < 4; b++)
#pragma unroll
            for (int c = 0; c < 4; c++) acc[a][b][c] = 0.f;

    // ---- stage loader ----
    auto load_stage = [&](int buf, int c) {
        int reg = (c >= 2 * kreg) ? 2 : ((c >= kreg) ? 1 : 0);
        int koff = (c - reg * kreg) * 64;
        const __nv_bfloat16* As = ((reg == 2) ? A1 : A0) + (size_t)(m0 + lrow) * K + koff;
        const __nv_bfloat16* Bs = ((reg == 1) ? B1 : B0) + (size_t)(n0 + lrow) * K + koff;
        uint32_t ab = smb + buf * (STAGE_ELEMS * 2);
        uint32_t bb = ab + TILE_ELEMS * 2;
        uint32_t rb = (uint32_t)lrow * 128;
#pragma unroll
        for (int ch = 0; ch < 4; ch++) {
            uint32_t off = rb + (lcb + ch) * 16;
            uint32_t dsw = swz(off);
            asm volatile("cp.async.cg.shared.global [%0], [%1], 16;"
                         :: "r"(ab + dsw), "l"(As + (lcb + ch) * 8));
            asm volatile("cp.async.cg.shared.global [%0], [%1], 16;"
                         :: "r"(bb + dsw), "l"(Bs + (lcb + ch) * 8));
        }
        asm volatile("cp.async.commit_group;" ::: "memory");
    };

    load_stage(0, 0);

    for (int c = 0; c < nk; c++) {
        if (c + 1 < nk) {
            load_stage((c + 1) & 1, c + 1);
            asm volatile("cp.async.wait_group 1;" ::: "memory");
        } else {
            asm volatile("cp.async.wait_group 0;" ::: "memory");
        }
        __syncthreads();

        const uint32_t ab = smb + (c & 1) * (STAGE_ELEMS * 2);
        const uint32_t bb = ab + TILE_ELEMS * 2;
#pragma unroll
        for (int ks = 0; ks < 4; ks++) {
            uint32_t af[4][4], bf[4][2];
#pragma unroll
            for (int mt = 0; mt < 4; mt++) {
                uint32_t addr = ab + swz(arow_b[mt] + ks * 32);
                asm volatile("ldmatrix.sync.aligned.m8n8.x4.shared.b16 {%0,%1,%2,%3}, [%4];"
                             : "=r"(af[mt][0]), "=r"(af[mt][1]), "=r"(af[mt][2]), "=r"(af[mt][3])
                             : "r"(addr));
            }
#pragma unroll
            for (int nt = 0; nt < 4; nt++) {
                uint32_t addr = bb + swz(brow_b[nt] + ks * 32);
                asm volatile("ldmatrix.sync.aligned.m8n8.x2.shared.b16 {%0,%1}, [%2];"
                             : "=r"(bf[nt][0]), "=r"(bf[nt][1]) : "r"(addr));
            }
#pragma unroll
            for (int mt = 0; mt < 4; mt++)
#pragma unroll
                for (int nt = 0; nt < 4; nt++) {
                    asm volatile(
                        "mma.sync.aligned.m16n8k16.row.col.f32.bf16.bf16.f32 "
                        "{%0,%1,%2,%3}, {%4,%5,%6,%7}, {%8,%9}, {%0,%1,%2,%3};"
                        : "+f"(acc[mt][nt][0]), "+f"(acc[mt][nt][1]),
                          "+f"(acc[mt][nt][2]), "+f"(acc[mt][nt][3])
                        : "r"(af[mt][0]), "r"(af[mt][1]), "r"(af[mt][2]), "r"(af[mt][3]),
                          "r"(bf[nt][0]), "r"(bf[nt][1]));
                }
        }
        __syncthreads();
    }

    // ---- epilogue: direct fp32 stores ----
#pragma unroll
    for (int mt = 0; mt < 4; mt++) {
        int row = m0 + wm + mt * 16 + (lane >> 2);
#pragma unroll
        for (int nt = 0; nt < 4; nt++) {
            int col = n0 + wn + nt * 8 + (lane & 3) * 2;
            float2 v0 = make_float2(acc[mt][nt][0], acc[mt][nt][1]);
            float2 v1 = make_float2(acc[mt][nt][2], acc[mt][nt][3]);
            if (bias) {
                float b0 = bias[col], b1 = bias[col + 1];
                v0.x += b0; v0.y += b1; v1.x += b0; v1.y += b1;
            }
            *(float2*)&C[(size_t)row * ldc + col] = v0;
            *(float2*)&C[(size_t)(row + 8) * ldc + col] = v1;
        }
    }
}

// ---------------- fused conv + SiLU + softplus + SSM scan + gate + RMSnorm ------
__global__ void __launch_bounds__(512, 1) scan_kernel(
    const float* __restrict__ Z,
    const float* __restrict__ conv_w, const float* __restrict__ conv_b,
    const float* __restrict__ dt_bias, const float* __restrict__ A_log,
    const float* __restrict__ Dv, const float* __restrict__ norm_w,
    int vertical, int ycol_off)
{
    const int tid  = threadIdx.x;
    const int head = tid >> 6;
    const int s    = blockIdx.x;

    int base, stride;
    if (vertical) { int b = s >> 6, w = s & 63; base = b * 4096 + w; stride = 64; }
    else          { base = s * 64; stride = 1; }

    __shared__ __align__(16) float ring[4][CONV_CH];
    __shared__ __align__(16) float Bsh[64];
    __shared__ __align__(16) float Csh[64];
    __shared__ float dt_s[8], dA_s[8], Aneg_s[8], dtb_s[8];
    __shared__ float red[16];
    __shared__ float s_inv;

    for (int i = tid; i < 4 * CONV_CH; i += 512) (&ring[0][0])[i] = 0.f;
    if (tid < 8) { Aneg_s[tid] = -expf(A_log[tid]); dtb_s[tid] = dt_bias[tid]; }

    const float w0 = conv_w[tid * 4 + 0], w1 = conv_w[tid * 4 + 1];
    const float w2 = conv_w[tid * 4 + 2], w3 = conv_w[tid * 4 + 3];
    const float cb = conv_b[tid];
    float u0 = 0.f, u1 = 0.f, u2 = 0.f, u3 = 0.f, cb2 = 0.f;
    const int c2 = 512 + tid;
    if (tid < 128) {
        u0 = conv_w[c2 * 4 + 0]; u1 = conv_w[c2 * 4 + 1];
        u2 = conv_w[c2 * 4 + 2]; u3 = conv_w[c2 * 4 + 3];
        cb2 = conv_b[c2];
    }
    const float Dh = Dv[head];
    const float nw = norm_w[tid];

    float h[64];
#pragma unroll
    for (int n = 0; n < 64; n++) h[n] = 0.f;

    __syncthreads();

    for (int t = 0; t < SEQ; t++) {
        const int rtok = base + t * stride;
        const float* row = Z + (size_t)rtok * NPAD1;
        const int slot = t & 3;
        ring[slot][tid] = row[512 + tid];
        if (tid < 128) ring[slot][512 + tid] = row[1024 + tid];
        const float z = row[tid];
        if (tid < 8) {
            float draw = row[1152 + tid] + dtb_s[tid];
            float dt = (draw > 20.f) ? draw : log1pf(expf(draw));
            dt_s[tid] = dt;
            dA_s[tid] = expf(dt * Aneg_s[tid]);
        }
        __syncthreads();

        const int s0 = (t + 1) & 3, s1 = (t + 2) & 3, s2 = (t + 3) & 3, s3 = slot;
        float xv = cb;
        xv = fmaf(ring[s0][tid], w0, xv);
        xv = fmaf(ring[s1][tid], w1, xv);
        xv = fmaf(ring[s2][tid], w2, xv);
        xv = fmaf(ring[s3][tid], w3, xv);
        xv = xv / (1.f + expf(-xv));
        if (tid < 128) {
            float v = cb2;
            v = fmaf(ring[s0][c2], u0, v);
            v = fmaf(ring[s1][c2], u1, v);
            v = fmaf(ring[s2][c2], u2, v);
            v = fmaf(ring[s3][c2], u3, v);
            v = v / (1.f + expf(-v));
            if (tid < 64) Bsh[tid] = v; else Csh[tid - 64] = v;
        }
        __syncthreads();

        const float dA  = dA_s[head];
        const float dtx = dt_s[head] * xv;
        float y = 0.f;
#pragma unroll
        for (int n = 0; n < 64; n += 4) {
            float4 bv = *(const float4*)&Bsh[n];
            float4 cv = *(const float4*)&Csh[n];
            h[n + 0] = fmaf(h[n + 0], dA, dtx * bv.x); y = fmaf(h[n + 0], cv.x, y);
            h[n + 1] = fmaf(h[n + 1], dA, dtx * bv.y); y = fmaf(h[n + 1], cv.y, y);
            h[n + 2] = fmaf(h[n + 2], dA, dtx * bv.z); y = fmaf(h[n + 2], cv.z, y);
            h[n + 3] = fmaf(h[n + 3], dA, dtx * bv.w); y = fmaf(h[n + 3], cv.w, y);
        }
        y = fmaf(xv, Dh, y);

        float g = y * (z / (1.f + expf(-z)));
        float ss = g * g;
#pragma unroll
        for (int o = 16; o; o >>= 1) ss += __shfl_xor_sync(0xffffffffu, ss, o);
        if ((tid & 31) == 0) red[tid >> 5] = ss;
        __syncthreads();
        if (tid < 32) {
            float v = (tid < 16) ? red[tid] : 0.f;
#pragma unroll
            for (int o = 8; o; o >>= 1) v += __shfl_xor_sync(0xffffffffu, v, o);
            if (tid == 0) s_inv = rsqrtf(v * (1.0f / 512.0f) + 1e-5f);
        }
        __syncthreads();
        float val = g * s_inv * nw;
        __nv_bfloat16 hh = __float2bfloat16(val);
        size_t oidx = (size_t)rtok * KFIN + ycol_off + tid;
        g_Yhi[oidx] = hh;
        g_Ylo[oidx] = __float2bfloat16(val - __bfloat162float(hh));
    }
}

// ---------------- fold fc_w into out_w, emit bf16 split [n=256][k=1024] ---------
__global__ void __launch_bounds__(256) wcomb_kernel(
    const float* __restrict__ mh_out_w, const float* __restrict__ mv_out_w,
    const float* __restrict__ fc_w)
{
    const int d  = blockIdx.x;              // 0 = v (K rows 0-511), 1 = h (512-1023)
    const int k0 = blockIdx.y * 64;
    const int nb = blockIdx.z * 64;
    const float* ow = d ? mh_out_w : mv_out_w;
    const int fo = d ? 512 : 0;
    __shared__ float ows[128][64];
    const int kk = threadIdx.x & 63;
    const int n  = nb + (threadIdx.x >> 6) * 16;
    float acc[16];
#pragma unroll
    for (int i = 0; i < 16; i++) acc[i] = 0.f;

    for (int jo = 0; jo < 256; jo += 128) {
        for (int i = threadIdx.x; i < 128 * 64; i += 256) {
            int jj = i >> 6, c = i & 63;
            ows[jj][c] = ow[(size_t)(jo + jj) * 512 + k0 + c];
        }
        __syncthreads();
        for (int jj = 0; jj < 128; jj++) {
            float o = ows[jj][kk];
            int jidx = jo + jj;
#pragma unroll 4
            for (int i = 0; i < 16; i++) {
                float f = fc_w[(n + i) * 1024 + fo + jidx] +
                          fc_w[(n + i) * 1024 + fo + 256 + jidx];
                acc[i] = fmaf(o, f, acc[i]);
            }
        }
        __syncthreads();
    }
#pragma unroll
    for (int i = 0; i < 16; i++) {
        float val = acc[i];
        __nv_bfloat16 hh = __float2bfloat16(val);
        size_t idx = (size_t)(n + i) * KFIN + d * 512 + (k0 + kk);
        g_WcBhi[idx] = hh;
        g_WcBlo[idx] = __float2bfloat16(val - __bfloat162float(hh));
    }
}

// ---------------- launch ----------------
extern "C" void kernel_launch(void* const* d_in, const int* in_sizes, int n_in,
                              void* d_out, int out_size)
{
    (void)in_sizes; (void)n_in; (void)out_size;
    const float* x          = (const float*)d_in[0];
    const float* mh_in_w    = (const float*)d_in[1];
    const float* mh_conv_w  = (const float*)d_in[2];
    const float* mh_conv_b  = (const float*)d_in[3];
    const float* mh_dt_bias = (const float*)d_in[4];
    const float* mh_A_log   = (const float*)d_in[5];
    const float* mh_D       = (const float*)d_in[6];
    const float* mh_norm_w  = (const float*)d_in[7];
    const float* mh_out_w   = (const float*)d_in[8];
    const float* mv_in_w    = (const float*)d_in[9];
    const float* mv_conv_w  = (const float*)d_in[10];
    const float* mv_conv_b  = (const float*)d_in[11];
    const float* mv_dt_bias = (const float*)d_in[12];
    const float* mv_A_log   = (const float*)d_in[13];
    const float* mv_D       = (const float*)d_in[14];
    const float* mv_norm_w  = (const float*)d_in[15];
    const float* mv_out_w   = (const float*)d_in[16];
    const float* fc_w       = (const float*)d_in[17];
    const float* fc_b       = (const float*)d_in[18];
    float* out = (float*)d_out;

    float *Zh, *Zv;
    __nv_bfloat16 *Xhi, *Xlo, *Whhi, *Whlo, *Wvhi, *Wvlo, *Yhi, *Ylo, *WcBhi, *WcBlo;
    cudaGetSymbolAddress((void**)&Zh,   g_Zh);
    cudaGetSymbolAddress((void**)&Zv,   g_Zv);
    cudaGetSymbolAddress((void**)&Xhi,  g_Xhi);
    cudaGetSymbolAddress((void**)&Xlo,  g_Xlo);
    cudaGetSymbolAddress((void**)&Whhi, g_Whhi);
    cudaGetSymbolAddress((void**)&Whlo, g_Whlo);
    cudaGetSymbolAddress((void**)&Wvhi, g_Wvhi);
    cudaGetSymbolAddress((void**)&Wvlo, g_Wvlo);
    cudaGetSymbolAddress((void**)&Yhi,  g_Yhi);
    cudaGetSymbolAddress((void**)&Ylo,  g_Ylo);
    cudaGetSymbolAddress((void**)&WcBhi, g_WcBhi);
    cudaGetSymbolAddress((void**)&WcBlo, g_WcBlo);

    cudaFuncSetAttribute(gemm_mma, cudaFuncAttributeMaxDynamicSharedMemorySize, GSMEM);

    const dim3 g_in(NTOK / 128, NPAD1 / 128);    // (256, 10)
    const dim3 g_fin(NTOK / 128, D_MODEL / 128); // (256, 2)

    cvt_x_kernel<<<NTOK * D_MODEL / 4 / 256, 256>>>(x);
    prep_w_kernel<<<(NPAD1 * D_MODEL + 255) / 256, 256>>>(mh_in_w, Whhi, Whlo);
    prep_w_kernel<<<(NPAD1 * D_MODEL + 255) / 256, 256>>>(mv_in_w, Wvhi, Wvlo);
    wcomb_kernel<<<dim3(2, 8, 4), 256>>>(mh_out_w, mv_out_w, fc_w);

    gemm_mma<<<g_in, 256, GSMEM>>>(Xhi, Xlo, Whhi, Whlo, Zh, D_MODEL, NPAD1, nullptr);
    gemm_mma<<<g_in, 256, GSMEM>>>(Xhi, Xlo, Wvhi, Wvlo, Zv, D_MODEL, NPAD1, nullptr);

    scan_kernel<<<NSEQ, 512>>>(Zh, mh_conv_w, mh_conv_b, mh_dt_bias, mh_A_log,
                               mh_D, mh_norm_w, 0, 512);
    scan_kernel<<<NSEQ, 512>>>(Zv, mv_conv_w, mv_conv_b, mv_dt_bias, mv_A_log,
                               mv_D, mv_norm_w, 1, 0);

    gemm_mma<<<g_fin, 256, GSMEM>>>(Yhi, Ylo, WcBhi, WcBlo, out, KFIN, D_MODEL, fc_b);
}

// round 4
// speedup vs baseline: 1.6477x; 1.1197x over previous
#include <cuda_runtime.h>
#include <cuda_bf16.h>
#include <math.h>
#include <stdint.h>

#define D_MODEL   256
#define D_INNER   512
#define CONV_CH   640
#define D_IN_PROJ 1160
#define NPAD1     1280     // padded N for in-proj GEMM
#define SEQ       64
#define NSEQ      512
#define NTOK      32768
#define KFIN      1024     // concat K for fused output GEMM

// ---------------- scratch (static device memory; allocation-free) --------------
__device__ float         g_Zh  [(size_t)NTOK * NPAD1];
__device__ float         g_Zv  [(size_t)NTOK * NPAD1];
__device__ __nv_bfloat16 g_Xhi [(size_t)NTOK * D_MODEL];
__device__ __nv_bfloat16 g_Xlo [(size_t)NTOK * D_MODEL];
__device__ __nv_bfloat16 g_Whhi[(size_t)NPAD1 * D_MODEL];
__device__ __nv_bfloat16 g_Whlo[(size_t)NPAD1 * D_MODEL];
__device__ __nv_bfloat16 g_Wvhi[(size_t)NPAD1 * D_MODEL];
__device__ __nv_bfloat16 g_Wvlo[(size_t)NPAD1 * D_MODEL];
__device__ __nv_bfloat16 g_Yhi [(size_t)NTOK * KFIN];
__device__ __nv_bfloat16 g_Ylo [(size_t)NTOK * KFIN];
__device__ __nv_bfloat16 g_WcBhi[(size_t)D_MODEL * KFIN];
__device__ __nv_bfloat16 g_WcBlo[(size_t)D_MODEL * KFIN];

// ---------------- helpers ------------------------------------------------------
__device__ __forceinline__ uint32_t smem_u32(const void* p) {
    uint32_t a;
    asm("{ .reg .u64 t; cvta.to.shared.u64 t, %1; cvt.u32.u64 %0, t; }" : "=r"(a) : "l"(p));
    return a;
}
__device__ __forceinline__ uint32_t swz(uint32_t off) {
    return off ^ ((off >> 3) & 0x70);
}
#define CP16(dst, src) \
    asm volatile("cp.async.cg.shared.global [%0], [%1], 16;" :: "r"(dst), "l"(src))
#define CP_COMMIT() asm volatile("cp.async.commit_group;" ::: "memory")
#define CP_WAIT(n)  asm volatile("cp.async.wait_group %0;" :: "n"(n) : "memory")

// ---------------- conversion kernels -------------------------------------------
__global__ void cvt_x_kernel(const float* __restrict__ in) {
    size_t i = (size_t)blockIdx.x * 256 + threadIdx.x;
    float4 v = ((const float4*)in)[i];
    __nv_bfloat16 h0 = __float2bfloat16(v.x), h1 = __float2bfloat16(v.y);
    __nv_bfloat16 h2 = __float2bfloat16(v.z), h3 = __float2bfloat16(v.w);
    __nv_bfloat162 hi01; hi01.x = h0; hi01.y = h1;
    __nv_bfloat162 hi23; hi23.x = h2; hi23.y = h3;
    __nv_bfloat162 lo01, lo23;
    lo01.x = __float2bfloat16(v.x - __bfloat162float(h0));
    lo01.y = __float2bfloat16(v.y - __bfloat162float(h1));
    lo23.x = __float2bfloat16(v.z - __bfloat162float(h2));
    lo23.y = __float2bfloat16(v.w - __bfloat162float(h3));
    ((__nv_bfloat162*)g_Xhi)[2 * i]     = hi01;
    ((__nv_bfloat162*)g_Xhi)[2 * i + 1] = hi23;
    ((__nv_bfloat162*)g_Xlo)[2 * i]     = lo01;
    ((__nv_bfloat162*)g_Xlo)[2 * i + 1] = lo23;
}

__global__ void prep_w_kernel(const float* __restrict__ w,
                              __nv_bfloat16* __restrict__ whi,
                              __nv_bfloat16* __restrict__ wlo) {
    int i = blockIdx.x * 256 + threadIdx.x;
    if (i < NPAD1 * D_MODEL) {
        int n = i >> 8;
        float v = (n < D_IN_PROJ) ? w[i] : 0.f;
        __nv_bfloat16 h = __float2bfloat16(v);
        whi[i] = h;
        wlo[i] = __float2bfloat16(v - __bfloat162float(h));
    }
}

// ---------------- mma.sync split-bf16 GEMM --------------------------------------
// C = Ahi*Bhi + Ahi*Blo + Alo*Bhi. A:[M][K] k-major, B:[N][K] k-major.
// CTA 128 threads (4 warps 2x2), tile 128x128, warp 64x64, BK=64, 3 stages.
#define TILE_B   16384           // 128x64 bf16 bytes
#define STAGE_B  32768
#define NSTG     3
#define GSMEM    (NSTG * STAGE_B)

__global__ void __launch_bounds__(128, 2) gemm_mma(
    const __nv_bfloat16* __restrict__ A0, const __nv_bfloat16* __restrict__ A1,
    const __nv_bfloat16* __restrict__ B0, const __nv_bfloat16* __restrict__ B1,
    float* __restrict__ C, int K, int ldc, const float* __restrict__ bias)
{
    extern __shared__ __nv_bfloat16 sm[];
    const uint32_t smb = smem_u32(sm);
    const int tid = threadIdx.x, lane = tid & 31, wid = tid >> 5;
    const int m0 = blockIdx.x * 128, n0 = blockIdx.y * 128;
    const int wm = (wid & 1) * 64, wn = (wid >> 1) * 64;
    const int kreg = K >> 6, nk = 3 * kreg;

    uint32_t arow[4], brow[4];
#pragma unroll
    for (int mt = 0; mt < 4; mt++)
        arow[mt] = (uint32_t)(wm + mt * 16 + (lane & 15)) * 128 + (lane >> 4) * 16;
#pragma unroll
    for (int nb = 0; nb < 4; nb++)
        brow[nb] = (uint32_t)(wn + nb * 16 + (lane & 15)) * 128 + (lane >> 4) * 16;

    float acc[4][8][4];
#pragma unroll
    for (int a = 0; a < 4; a++)
#pragma unroll
        for (int b = 0; b < 8; b++)
#pragma unroll
            for (int c = 0; c < 4; c++) acc[a][b][c] = 0.f;

    auto load_stage = [&](int s, int c) {
        int reg = (c >= 2 * kreg) ? 2 : ((c >= kreg) ? 1 : 0);
        int koff = (c - reg * kreg) * 64;
        const __nv_bfloat16* As = ((reg == 2) ? A1 : A0) + (size_t)(m0 + tid) * K + koff;
        const __nv_bfloat16* Bs = ((reg == 1) ? B1 : B0) + (size_t)(n0 + tid) * K + koff;
        uint32_t ab = smb + s * STAGE_B;
        uint32_t bb = ab + TILE_B;
        uint32_t rb = (uint32_t)tid * 128;
#pragma unroll
        for (int ch = 0; ch < 8; ch++) {
            uint32_t dsw = swz(rb + ch * 16);
            CP16(ab + dsw, As + ch * 8);
            CP16(bb + dsw, Bs + ch * 8);
        }
        CP_COMMIT();
    };

    load_stage(0, 0);
    load_stage(1, 1);

    for (int c = 0; c < nk; c++) {
        if (c + 1 < nk) CP_WAIT(1); else CP_WAIT(0);
        __syncthreads();
        if (c + 2 < nk) load_stage((c + 2) % NSTG, c + 2);

        const uint32_t ab = smb + (c % NSTG) * STAGE_B;
        const uint32_t bb = ab + TILE_B;
#pragma unroll
        for (int ks = 0; ks < 4; ks++) {
            uint32_t af[4][4], bfr[4][4];
#pragma unroll
            for (int mt = 0; mt < 4; mt++) {
                uint32_t addr = ab + swz(arow[mt] + ks * 32);
                asm volatile("ldmatrix.sync.aligned.m8n8.x4.shared.b16 {%0,%1,%2,%3}, [%4];"
                             : "=r"(af[mt][0]), "=r"(af[mt][1]), "=r"(af[mt][2]), "=r"(af[mt][3])
                             : "r"(addr));
            }
#pragma unroll
            for (int nb = 0; nb < 4; nb++) {
                uint32_t addr = bb + swz(brow[nb] + ks * 32);
                asm volatile("ldmatrix.sync.aligned.m8n8.x4.shared.b16 {%0,%1,%2,%3}, [%4];"
                             : "=r"(bfr[nb][0]), "=r"(bfr[nb][1]), "=r"(bfr[nb][2]), "=r"(bfr[nb][3])
                             : "r"(addr));
            }
#pragma unroll
            for (int mt = 0; mt < 4; mt++)
#pragma unroll
                for (int nb = 0; nb < 4; nb++) {
                    asm volatile(
                        "mma.sync.aligned.m16n8k16.row.col.f32.bf16.bf16.f32 "
                        "{%0,%1,%2,%3}, {%4,%5,%6,%7}, {%8,%9}, {%0,%1,%2,%3};"
                        : "+f"(acc[mt][nb * 2][0]), "+f"(acc[mt][nb * 2][1]),
                          "+f"(acc[mt][nb * 2][2]), "+f"(acc[mt][nb * 2][3])
                        : "r"(af[mt][0]), "r"(af[mt][1]), "r"(af[mt][2]), "r"(af[mt][3]),
                          "r"(bfr[nb][0]), "r"(bfr[nb][2]));
                    asm volatile(
                        "mma.sync.aligned.m16n8k16.row.col.f32.bf16.bf16.f32 "
                        "{%0,%1,%2,%3}, {%4,%5,%6,%7}, {%8,%9}, {%0,%1,%2,%3};"
                        : "+f"(acc[mt][nb * 2 + 1][0]), "+f"(acc[mt][nb * 2 + 1][1]),
                          "+f"(acc[mt][nb * 2 + 1][2]), "+f"(acc[mt][nb * 2 + 1][3])
                        : "r"(af[mt][0]), "r"(af[mt][1]), "r"(af[mt][2]), "r"(af[mt][3]),
                          "r"(bfr[nb][1]), "r"(bfr[nb][3]));
                }
        }
    }

#pragma unroll
    for (int mt = 0; mt < 4; mt++) {
        int row = m0 + wm + mt * 16 + (lane >> 2);
#pragma unroll
        for (int nt = 0; nt < 8; nt++) {
            int col = n0 + wn + nt * 8 + (lane & 3) * 2;
            float2 v0 = make_float2(acc[mt][nt][0], acc[mt][nt][1]);
            float2 v1 = make_float2(acc[mt][nt][2], acc[mt][nt][3]);
            if (bias) {
                float b0 = bias[col], b1 = bias[col + 1];
                v0.x += b0; v0.y += b1; v1.x += b0; v1.y += b1;
            }
            *(float2*)&C[(size_t)row * ldc + col] = v0;
            *(float2*)&C[(size_t)(row + 8) * ldc + col] = v1;
        }
    }
}

// ---------------- fused conv + SiLU + softplus + SSM scan + gate + RMSnorm ------
// cp.async prefetch 2 iterations ahead: xBC -> 8-deep ring, z/dt -> 4-deep bufs.
__global__ void __launch_bounds__(512, 1) scan_kernel(
    const float* __restrict__ Z,
    const float* __restrict__ conv_w, const float* __restrict__ conv_b,
    const float* __restrict__ dt_bias, const float* __restrict__ A_log,
    const float* __restrict__ Dv, const float* __restrict__ norm_w,
    int vertical, int ycol_off)
{
    const int tid  = threadIdx.x;
    const int head = tid >> 6;
    const int s    = blockIdx.x;

    int base, stride;
    if (vertical) { int b = s >> 6, w = s & 63; base = b * 4096 + w; stride = 64; }
    else          { base = s * 64; stride = 1; }

    __shared__ __align__(16) float ring[8][CONV_CH];
    __shared__ __align__(16) float zbuf[4][512];
    __shared__ __align__(16) float dtb[4][8];
    __shared__ __align__(16) float Bsh[64];
    __shared__ __align__(16) float Csh[64];
    __shared__ float dt_s[8], dA_s[8], Aneg_s[8], dtb_s[8];
    __shared__ float red[16];

    for (int i = tid; i < 8 * CONV_CH; i += 512) (&ring[0][0])[i] = 0.f;
    if (tid < 8) { Aneg_s[tid] = -expf(A_log[tid]); dtb_s[tid] = dt_bias[tid]; }

    const float w0 = conv_w[tid * 4 + 0], w1 = conv_w[tid * 4 + 1];
    const float w2 = conv_w[tid * 4 + 2], w3 = conv_w[tid * 4 + 3];
    const float cb = conv_b[tid];
    float u0 = 0.f, u1 = 0.f, u2 = 0.f, u3 = 0.f, cb2 = 0.f;
    const int c2 = 512 + tid;
    if (tid < 128) {
        u0 = conv_w[c2 * 4 + 0]; u1 = conv_w[c2 * 4 + 1];
        u2 = conv_w[c2 * 4 + 2]; u3 = conv_w[c2 * 4 + 3];
        cb2 = conv_b[c2];
    }
    const float Dh = Dv[head];
    const float nw = norm_w[tid];

    float h[64];
#pragma unroll
    for (int n = 0; n < 64; n++) h[n] = 0.f;

    const uint32_t ring_b = smem_u32(&ring[0][0]);
    const uint32_t zbuf_b = smem_u32(&zbuf[0][0]);
    const uint32_t dtb_b  = smem_u32(&dtb[0][0]);

    auto prefetch = [&](int tt) {
        if (tt < SEQ) {
            const float* row = Z + (size_t)(base + tt * stride) * NPAD1;
            if (tid < 160)       CP16(ring_b + (tt & 7) * (CONV_CH * 4) + tid * 16, row + 512 + tid * 4);
            else if (tid < 288)  CP16(zbuf_b + (tt & 3) * 2048 + (tid - 160) * 16, row + (tid - 160) * 4);
            else if (tid < 290)  CP16(dtb_b + (tt & 3) * 32 + (tid - 288) * 16, row + 1152 + (tid - 288) * 4);
        }
        CP_COMMIT();
    };

    __syncthreads();   // ring zero-fill visible before cp.async writes
    prefetch(0);
    prefetch(1);

    for (int t = 0; t < SEQ; t++) {
        if (t < SEQ - 1) CP_WAIT(1); else CP_WAIT(0);
        __syncthreads();
        prefetch(t + 2);

        const int slot = t & 7;
        if (tid < 8) {
            float draw = dtb[t & 3][tid] + dtb_s[tid];
            float dt = (draw > 20.f) ? draw : log1pf(expf(draw));
            dt_s[tid] = dt;
            dA_s[tid] = expf(dt * Aneg_s[tid]);
        }

        const int s0 = (t + 5) & 7, s1 = (t + 6) & 7, s2 = (t + 7) & 7, s3 = slot;
        float xv = cb;
        xv = fmaf(ring[s0][tid], w0, xv);
        xv = fmaf(ring[s1][tid], w1, xv);
        xv = fmaf(ring[s2][tid], w2, xv);
        xv = fmaf(ring[s3][tid], w3, xv);
        xv = xv / (1.f + expf(-xv));
        if (tid < 128) {
            float v = cb2;
            v = fmaf(ring[s0][c2], u0, v);
            v = fmaf(ring[s1][c2], u1, v);
            v = fmaf(ring[s2][c2], u2, v);
            v = fmaf(ring[s3][c2], u3, v);
            v = v / (1.f + expf(-v));
            if (tid < 64) Bsh[tid] = v; else Csh[tid - 64] = v;
        }
        __syncthreads();

        const float dA  = dA_s[head];
        const float dtx = dt_s[head] * xv;
        float y = 0.f;
#pragma unroll
        for (int n = 0; n < 64; n += 4) {
            float4 bv = *(const float4*)&Bsh[n];
            float4 cv = *(const float4*)&Csh[n];
            h[n + 0] = fmaf(h[n + 0], dA, dtx * bv.x); y = fmaf(h[n + 0], cv.x, y);
            h[n + 1] = fmaf(h[n + 1], dA, dtx * bv.y); y = fmaf(h[n + 1], cv.y, y);
            h[n + 2] = fmaf(h[n + 2], dA, dtx * bv.z); y = fmaf(h[n + 2], cv.z, y);
            h[n + 3] = fmaf(h[n + 3], dA, dtx * bv.w); y = fmaf(h[n + 3], cv.w, y);
        }
        y = fmaf(xv, Dh, y);

        const float z = zbuf[t & 3][tid];
        float g = y * (z / (1.f + expf(-z)));
        float ss = g * g;
#pragma unroll
        for (int o = 16; o; o >>= 1) ss += __shfl_xor_sync(0xffffffffu, ss, o);
        if ((tid & 31) == 0) red[tid >> 5] = ss;
        __syncthreads();
        // redundant final reduce in every warp (no broadcast barrier)
        float v = red[tid & 15];
#pragma unroll
        for (int o = 8; o; o >>= 1) v += __shfl_xor_sync(0xffffffffu, v, o);
        float s_inv = rsqrtf(v * (1.0f / 512.0f) + 1e-5f);

        float val = g * s_inv * nw;
        __nv_bfloat16 hh = __float2bfloat16(val);
        size_t oidx = (size_t)(base + t * stride) * KFIN + ycol_off + tid;
        g_Yhi[oidx] = hh;
        g_Ylo[oidx] = __float2bfloat16(val - __bfloat162float(hh));
    }
}

// ---------------- fold fc_w into out_w, smem-tiled ------------------------------
// C[d][k][n] = sum_j ow[j][k] * (fc[n][fo+j] + fc[n][fo+256+j])
__global__ void __launch_bounds__(256) wcomb_kernel(
    const float* __restrict__ mh_out_w, const float* __restrict__ mv_out_w,
    const float* __restrict__ fc_w)
{
    const int d  = blockIdx.x;
    const int k0 = blockIdx.y * 64;
    const int nb = blockIdx.z * 64;
    const float* ow = d ? mh_out_w : mv_out_w;
    const int fo = d ? 512 : 0;
    __shared__ float ows[64][65];   // [j][k]
    __shared__ float fs[64][65];    // [n][j]
    const int kk = threadIdx.x & 63;
    const int ng = threadIdx.x >> 6;       // 0..3
    float acc[16];
#pragma unroll
    for (int i = 0; i < 16; i++) acc[i] = 0.f;

    for (int jo = 0; jo < 256; jo += 64) {
        for (int idx = threadIdx.x; idx < 64 * 64; idx += 256) {
            int j = idx >> 6, c = idx & 63;
            ows[j][c] = ow[(size_t)(jo + j) * 512 + k0 + c];
            int n = idx >> 6, jj = idx & 63;
            fs[n][jj] = fc_w[(size_t)(nb + n) * 1024 + fo + jo + jj] +
                        fc_w[(size_t)(nb + n) * 1024 + fo + 256 + jo + jj];
        }
        __syncthreads();
#pragma unroll 4
        for (int j = 0; j < 64; j++) {
            float o = ows[j][kk];
#pragma unroll
            for (int i = 0; i < 16; i++)
                acc[i] = fmaf(o, fs[ng * 16 + i][j], acc[i]);
        }
        __syncthreads();
    }
#pragma unroll
    for (int i = 0; i < 16; i++) {
        float val = acc[i];
        __nv_bfloat16 hh = __float2bfloat16(val);
        size_t idx = (size_t)(nb + ng * 16 + i) * KFIN + d * 512 + (k0 + kk);
        g_WcBhi[idx] = hh;
        g_WcBlo[idx] = __float2bfloat16(val - __bfloat162float(hh));
    }
}

// ---------------- launch ----------------
extern "C" void kernel_launch(void* const* d_in, const int* in_sizes, int n_in,
                              void* d_out, int out_size)
{
    (void)in_sizes; (void)n_in; (void)out_size;
    const float* x          = (const float*)d_in[0];
    const float* mh_in_w    = (const float*)d_in[1];
    const float* mh_conv_w  = (const float*)d_in[2];
    const float* mh_conv_b  = (const float*)d_in[3];
    const float* mh_dt_bias = (const float*)d_in[4];
    const float* mh_A_log   = (const float*)d_in[5];
    const float* mh_D       = (const float*)d_in[6];
    const float* mh_norm_w  = (const float*)d_in[7];
    const float* mh_out_w   = (const float*)d_in[8];
    const float* mv_in_w    = (const float*)d_in[9];
    const float* mv_conv_w  = (const float*)d_in[10];
    const float* mv_conv_b  = (const float*)d_in[11];
    const float* mv_dt_bias = (const float*)d_in[12];
    const float* mv_A_log   = (const float*)d_in[13];
    const float* mv_D       = (const float*)d_in[14];
    const float* mv_norm_w  = (const float*)d_in[15];
    const float* mv_out_w   = (const float*)d_in[16];
    const float* fc_w       = (const float*)d_in[17];
    const float* fc_b       = (const float*)d_in[18];
    float* out = (float*)d_out;

    float *Zh, *Zv;
    __nv_bfloat16 *Xhi, *Xlo, *Whhi, *Whlo, *Wvhi, *Wvlo, *Yhi, *Ylo, *WcBhi, *WcBlo;
    cudaGetSymbolAddress((void**)&Zh,   g_Zh);
    cudaGetSymbolAddress((void**)&Zv,   g_Zv);
    cudaGetSymbolAddress((void**)&Xhi,  g_Xhi);
    cudaGetSymbolAddress((void**)&Xlo,  g_Xlo);
    cudaGetSymbolAddress((void**)&Whhi, g_Whhi);
    cudaGetSymbolAddress((void**)&Whlo, g_Whlo);
    cudaGetSymbolAddress((void**)&Wvhi, g_Wvhi);
    cudaGetSymbolAddress((void**)&Wvlo, g_Wvlo);
    cudaGetSymbolAddress((void**)&Yhi,  g_Yhi);
    cudaGetSymbolAddress((void**)&Ylo,  g_Ylo);
    cudaGetSymbolAddress((void**)&WcBhi, g_WcBhi);
    cudaGetSymbolAddress((void**)&WcBlo, g_WcBlo);

    cudaFuncSetAttribute(gemm_mma, cudaFuncAttributeMaxDynamicSharedMemorySize, GSMEM);

    const dim3 g_in(NTOK / 128, NPAD1 / 128);    // (256, 10)
    const dim3 g_fin(NTOK / 128, D_MODEL / 128); // (256, 2)

    cvt_x_kernel<<<NTOK * D_MODEL / 4 / 256, 256>>>(x);
    prep_w_kernel<<<(NPAD1 * D_MODEL + 255) / 256, 256>>>(mh_in_w, Whhi, Whlo);
    prep_w_kernel<<<(NPAD1 * D_MODEL + 255) / 256, 256>>>(mv_in_w, Wvhi, Wvlo);
    wcomb_kernel<<<dim3(2, 8, 4), 256>>>(mh_out_w, mv_out_w, fc_w);

    gemm_mma<<<g_in, 128, GSMEM>>>(Xhi, Xlo, Whhi, Whlo, Zh, D_MODEL, NPAD1, nullptr);
    gemm_mma<<<g_in, 128, GSMEM>>>(Xhi, Xlo, Wvhi, Wvlo, Zv, D_MODEL, NPAD1, nullptr);

    scan_kernel<<<NSEQ, 512>>>(Zh, mh_conv_w, mh_conv_b, mh_dt_bias, mh_A_log,
                               mh_D, mh_norm_w, 0, 512);
    scan_kernel<<<NSEQ, 512>>>(Zv, mv_conv_w, mv_conv_b, mv_dt_bias, mv_A_log,
                               mv_D, mv_norm_w, 1, 0);

    gemm_mma<<<g_fin, 128, GSMEM>>>(Yhi, Ylo, WcBhi, WcBlo, out, KFIN, D_MODEL, fc_b);
}

// round 5
// speedup vs baseline: 1.9170x; 1.1634x over previous
#include <cuda_runtime.h>
#include <cuda_bf16.h>
#include <math.h>
#include <stdint.h>

#define D_MODEL   256
#define D_INNER   512
#define CONV_CH   640
#define D_IN_PROJ 1160
#define NPAD1     1280
#define SEQ       64
#define NSEQ      512
#define NTOK      32768
#define KFIN      1024

// ---------------- scratch ------------------------------------------------------
__device__ float         g_Zh  [(size_t)NTOK * NPAD1];
__device__ float         g_Zv  [(size_t)NTOK * NPAD1];
__device__ __nv_bfloat16 g_Xhi [(size_t)NTOK * D_MODEL];
__device__ __nv_bfloat16 g_Xlo [(size_t)NTOK * D_MODEL];
__device__ __nv_bfloat16 g_Whhi[(size_t)NPAD1 * D_MODEL];
__device__ __nv_bfloat16 g_Whlo[(size_t)NPAD1 * D_MODEL];
__device__ __nv_bfloat16 g_Wvhi[(size_t)NPAD1 * D_MODEL];
__device__ __nv_bfloat16 g_Wvlo[(size_t)NPAD1 * D_MODEL];
__device__ __nv_bfloat16 g_Yhi [(size_t)NTOK * KFIN];
__device__ __nv_bfloat16 g_Ylo [(size_t)NTOK * KFIN];
__device__ __nv_bfloat16 g_WcBhi[(size_t)D_MODEL * KFIN];
__device__ __nv_bfloat16 g_WcBlo[(size_t)D_MODEL * KFIN];

// ---------------- helpers ------------------------------------------------------
__device__ __forceinline__ uint32_t smem_u32(const void* p) {
    uint32_t a;
    asm("{ .reg .u64 t; cvta.to.shared.u64 t, %1; cvt.u32.u64 %0, t; }" : "=r"(a) : "l"(p));
    return a;
}
__device__ __forceinline__ uint32_t swz(uint32_t off) {
    return off ^ ((off >> 3) & 0x70);
}
#define CP16(dst, src) \
    asm volatile("cp.async.cg.shared.global [%0], [%1], 16;" :: "r"(dst), "l"(src))
#define CP_COMMIT() asm volatile("cp.async.commit_group;" ::: "memory")
#define CP_WAIT(n)  asm volatile("cp.async.wait_group %0;" :: "n"(n) : "memory")

typedef unsigned long long ull;
__device__ __forceinline__ ull pack2(float lo, float hi) {
    ull r; asm("mov.b64 %0, {%1, %2};" : "=l"(r) : "f"(lo), "f"(hi)); return r;
}
#define FMA_X2(d, a, b, c) \
    asm("fma.rn.f32x2 %0, %1, %2, %3;" : "=l"(d) : "l"(a), "l"(b), "l"(c))
#define MUL_X2(d, a, b) \
    asm("mul.rn.f32x2 %0, %1, %2;" : "=l"(d) : "l"(a), "l"(b))

// ---------------- conversion kernels -------------------------------------------
__global__ void cvt_x_kernel(const float* __restrict__ in) {
    size_t i = (size_t)blockIdx.x * 256 + threadIdx.x;
    float4 v = ((const float4*)in)[i];
    __nv_bfloat16 h0 = __float2bfloat16(v.x), h1 = __float2bfloat16(v.y);
    __nv_bfloat16 h2 = __float2bfloat16(v.z), h3 = __float2bfloat16(v.w);
    __nv_bfloat162 hi01; hi01.x = h0; hi01.y = h1;
    __nv_bfloat162 hi23; hi23.x = h2; hi23.y = h3;
    __nv_bfloat162 lo01, lo23;
    lo01.x = __float2bfloat16(v.x - __bfloat162float(h0));
    lo01.y = __float2bfloat16(v.y - __bfloat162float(h1));
    lo23.x = __float2bfloat16(v.z - __bfloat162float(h2));
    lo23.y = __float2bfloat16(v.w - __bfloat162float(h3));
    ((__nv_bfloat162*)g_Xhi)[2 * i]     = hi01;
    ((__nv_bfloat162*)g_Xhi)[2 * i + 1] = hi23;
    ((__nv_bfloat162*)g_Xlo)[2 * i]     = lo01;
    ((__nv_bfloat162*)g_Xlo)[2 * i + 1] = lo23;
}

__global__ void prep_w_kernel(const float* __restrict__ w,
                              __nv_bfloat16* __restrict__ whi,
                              __nv_bfloat16* __restrict__ wlo) {
    int i = blockIdx.x * 256 + threadIdx.x;
    if (i < NPAD1 * D_MODEL) {
        int n = i >> 8;
        float v = (n < D_IN_PROJ) ? w[i] : 0.f;
        __nv_bfloat16 h = __float2bfloat16(v);
        whi[i] = h;
        wlo[i] = __float2bfloat16(v - __bfloat162float(h));
    }
}

// ---------------- mma.sync split-bf16 GEMM --------------------------------------
// C = Ahi*Bhi + Ahi*Blo + Alo*Bhi, all terms in ONE K pass per chunk.
// Tile 256x128, 8 warps (4x2), warp 64x64, BK=64, 2-stage ping-pong.
#define BM 256
#define BN 128
#define A_TILE_B 32768          // 256x64 bf16
#define B_TILE_B 16384          // 128x64 bf16
#define STAGE_B  (2 * A_TILE_B + 2 * B_TILE_B)   // 98304
#define GSMEM    (2 * STAGE_B)                    // 196608

__global__ void __launch_bounds__(256, 1) gemm_mma(
    const __nv_bfloat16* __restrict__ Ahi, const __nv_bfloat16* __restrict__ Alo,
    const __nv_bfloat16* __restrict__ Bhi, const __nv_bfloat16* __restrict__ Blo,
    float* __restrict__ C, int K, int ldc, const float* __restrict__ bias)
{
    extern __shared__ __nv_bfloat16 sm[];
    const uint32_t smb = smem_u32(sm);
    const int tid = threadIdx.x, lane = tid & 31, wid = tid >> 5;
    const int m0 = blockIdx.x * BM, n0 = blockIdx.y * BN;
    const int wm = (wid & 3) * 64, wn = (wid >> 2) * 64;
    const int nk = K >> 6;

    uint32_t arow[4], brow[4];
#pragma unroll
    for (int mt = 0; mt < 4; mt++)
        arow[mt] = (uint32_t)(wm + mt * 16 + (lane & 15)) * 128 + (lane >> 4) * 16;
#pragma unroll
    for (int nb = 0; nb < 4; nb++)
        brow[nb] = (uint32_t)(wn + nb * 16 + (lane & 15)) * 128 + (lane >> 4) * 16;

    float acc[4][8][4];
#pragma unroll
    for (int a = 0; a < 4; a++)
#pragma unroll
        for (int b = 0; b < 8; b++)
#pragma unroll
            for (int c = 0; c < 4; c++) acc[a][b][c] = 0.f;

    auto load_stage = [&](int s, int c) {
        const int koff = c * 64;
        const uint32_t base = smb + s * STAGE_B;
        const __nv_bfloat16* pAhi = Ahi + (size_t)(m0 + tid) * K + koff;
        const __nv_bfloat16* pAlo = Alo + (size_t)(m0 + tid) * K + koff;
        const uint32_t rb = (uint32_t)tid * 128;
#pragma unroll
        for (int ch = 0; ch < 8; ch++) {
            uint32_t d = swz(rb + ch * 16);
            CP16(base + d, pAhi + ch * 8);
            CP16(base + A_TILE_B + d, pAlo + ch * 8);
        }
        const int br = tid & 127;
        const __nv_bfloat16* pB = ((tid < 128) ? Bhi : Blo) + (size_t)(n0 + br) * K + koff;
        const uint32_t bbase = base + 2 * A_TILE_B + ((tid < 128) ? 0 : B_TILE_B);
        const uint32_t rb2 = (uint32_t)br * 128;
#pragma unroll
        for (int ch = 0; ch < 8; ch++)
            CP16(bbase + swz(rb2 + ch * 16), pB + ch * 8);
        CP_COMMIT();
    };

    load_stage(0, 0);

    for (int c = 0; c < nk; c++) {
        if (c + 1 < nk) { load_stage((c + 1) & 1, c + 1); CP_WAIT(1); }
        else            { CP_WAIT(0); }
        __syncthreads();

        const uint32_t base = smb + (c & 1) * STAGE_B;
        const uint32_t aHiB = base, aLoB = base + A_TILE_B;
        const uint32_t bHiB = base + 2 * A_TILE_B, bLoB = bHiB + B_TILE_B;
#pragma unroll
        for (int ks = 0; ks < 4; ks++) {
            uint32_t ahi[4][4], alo[4][4], bhi[4][4], blo[4][4];
#pragma unroll
            for (int mt = 0; mt < 4; mt++) {
                uint32_t sw = swz(arow[mt] + ks * 32);
                asm volatile("ldmatrix.sync.aligned.m8n8.x4.shared.b16 {%0,%1,%2,%3}, [%4];"
                             : "=r"(ahi[mt][0]), "=r"(ahi[mt][1]), "=r"(ahi[mt][2]), "=r"(ahi[mt][3])
                             : "r"(aHiB + sw));
                asm volatile("ldmatrix.sync.aligned.m8n8.x4.shared.b16 {%0,%1,%2,%3}, [%4];"
                             : "=r"(alo[mt][0]), "=r"(alo[mt][1]), "=r"(alo[mt][2]), "=r"(alo[mt][3])
                             : "r"(aLoB + sw));
            }
#pragma unroll
            for (int nb = 0; nb < 4; nb++) {
                uint32_t sw = swz(brow[nb] + ks * 32);
                asm volatile("ldmatrix.sync.aligned.m8n8.x4.shared.b16 {%0,%1,%2,%3}, [%4];"
                             : "=r"(bhi[nb][0]), "=r"(bhi[nb][1]), "=r"(bhi[nb][2]), "=r"(bhi[nb][3])
                             : "r"(bHiB + sw));
                asm volatile("ldmatrix.sync.aligned.m8n8.x4.shared.b16 {%0,%1,%2,%3}, [%4];"
                             : "=r"(blo[nb][0]), "=r"(blo[nb][1]), "=r"(blo[nb][2]), "=r"(blo[nb][3])
                             : "r"(bLoB + sw));
            }
#define MMA_PASS(AF, BF)                                                              \
            _Pragma("unroll")                                                         \
            for (int mt = 0; mt < 4; mt++)                                            \
                _Pragma("unroll")                                                     \
                for (int nb = 0; nb < 4; nb++) {                                      \
                    asm volatile(                                                     \
                        "mma.sync.aligned.m16n8k16.row.col.f32.bf16.bf16.f32 "        \
                        "{%0,%1,%2,%3}, {%4,%5,%6,%7}, {%8,%9}, {%0,%1,%2,%3};"       \
                        : "+f"(acc[mt][nb * 2][0]), "+f"(acc[mt][nb * 2][1]),         \
                          "+f"(acc[mt][nb * 2][2]), "+f"(acc[mt][nb * 2][3])          \
                        : "r"(AF[mt][0]), "r"(AF[mt][1]), "r"(AF[mt][2]), "r"(AF[mt][3]), \
                          "r"(BF[nb][0]), "r"(BF[nb][2]));                            \
                    asm volatile(                                                     \
                        "mma.sync.aligned.m16n8k16.row.col.f32.bf16.bf16.f32 "        \
                        "{%0,%1,%2,%3}, {%4,%5,%6,%7}, {%8,%9}, {%0,%1,%2,%3};"       \
                        : "+f"(acc[mt][nb * 2 + 1][0]), "+f"(acc[mt][nb * 2 + 1][1]), \
                          "+f"(acc[mt][nb * 2 + 1][2]), "+f"(acc[mt][nb * 2 + 1][3])  \
                        : "r"(AF[mt][0]), "r"(AF[mt][1]), "r"(AF[mt][2]), "r"(AF[mt][3]), \
                          "r"(BF[nb][1]), "r"(BF[nb][3]));                            \
                }
            MMA_PASS(ahi, bhi)
            MMA_PASS(ahi, blo)
            MMA_PASS(alo, bhi)
#undef MMA_PASS
        }
        __syncthreads();
    }

#pragma unroll
    for (int mt = 0; mt < 4; mt++) {
        int row = m0 + wm + mt * 16 + (lane >> 2);
#pragma unroll
        for (int nt = 0; nt < 8; nt++) {
            int col = n0 + wn + nt * 8 + (lane & 3) * 2;
            float2 v0 = make_float2(acc[mt][nt][0], acc[mt][nt][1]);
            float2 v1 = make_float2(acc[mt][nt][2], acc[mt][nt][3]);
            if (bias) {
                float b0 = bias[col], b1 = bias[col + 1];
                v0.x += b0; v0.y += b1; v1.x += b0; v1.y += b1;
            }
            *(float2*)&C[(size_t)row * ldc + col] = v0;
            *(float2*)&C[(size_t)(row + 8) * ldc + col] = v1;
        }
    }
}

// ---------------- fused conv + SiLU + softplus + SSM scan + gate + RMSnorm ------
__global__ void __launch_bounds__(512, 1) scan_kernel(
    const float* __restrict__ Z,
    const float* __restrict__ conv_w, const float* __restrict__ conv_b,
    const float* __restrict__ dt_bias, const float* __restrict__ A_log,
    const float* __restrict__ Dv, const float* __restrict__ norm_w,
    int vertical, int ycol_off)
{
    const int tid  = threadIdx.x;
    const int head = tid >> 6;
    const int s    = blockIdx.x;

    int base, stride;
    if (vertical) { int b = s >> 6, w = s & 63; base = b * 4096 + w; stride = 64; }
    else          { base = s * 64; stride = 1; }

    __shared__ __align__(16) float ring[8][CONV_CH];
    __shared__ __align__(16) float zbuf[4][512];
    __shared__ __align__(16) float dtbuf[4][8];
    __shared__ __align__(16) float Bsh[64];
    __shared__ __align__(16) float Csh[64];
    __shared__ float dt_s[8], dA_s[8], Aneg_s[8], dtb_s[8];
    __shared__ float red[16];

    for (int i = tid; i < 8 * CONV_CH; i += 512) (&ring[0][0])[i] = 0.f;
    if (tid < 8) { Aneg_s[tid] = -expf(A_log[tid]); dtb_s[tid] = dt_bias[tid]; }

    const float w0 = conv_w[tid * 4 + 0], w1 = conv_w[tid * 4 + 1];
    const float w2 = conv_w[tid * 4 + 2], w3 = conv_w[tid * 4 + 3];
    const float cb = conv_b[tid];
    float u0 = 0.f, u1 = 0.f, u2 = 0.f, u3 = 0.f, cb2 = 0.f;
    const int c2 = 512 + tid;
    if (tid < 128) {
        u0 = conv_w[c2 * 4 + 0]; u1 = conv_w[c2 * 4 + 1];
        u2 = conv_w[c2 * 4 + 2]; u3 = conv_w[c2 * 4 + 3];
        cb2 = conv_b[c2];
    }
    const float Dh = Dv[head];
    const float nw = norm_w[tid];

    ull h2[32];
#pragma unroll
    for (int n = 0; n < 32; n++) h2[n] = pack2(0.f, 0.f);

    const uint32_t ring_b = smem_u32(&ring[0][0]);
    const uint32_t zbuf_b = smem_u32(&zbuf[0][0]);
    const uint32_t dtb_b  = smem_u32(&dtbuf[0][0]);

    auto prefetch = [&](int tt) {
        if (tt < SEQ) {
            const float* row = Z + (size_t)(base + tt * stride) * NPAD1;
            if (tid < 160)       CP16(ring_b + (tt & 7) * (CONV_CH * 4) + tid * 16, row + 512 + tid * 4);
            else if (tid < 288)  CP16(zbuf_b + (tt & 3) * 2048 + (tid - 160) * 16, row + (tid - 160) * 4);
            else if (tid < 290)  CP16(dtb_b + (tt & 3) * 32 + (tid - 288) * 16, row + 1152 + (tid - 288) * 4);
        }
        CP_COMMIT();
    };

    __syncthreads();
    prefetch(0);
    prefetch(1);

    for (int t = 0; t < SEQ; t++) {
        if (t < SEQ - 1) CP_WAIT(1); else CP_WAIT(0);
        __syncthreads();
        prefetch(t + 2);

        const int slot = t & 7;
        if (tid < 8) {
            float draw = dtbuf[t & 3][tid] + dtb_s[tid];
            float dt = (draw > 20.f) ? draw : log1pf(expf(draw));
            dt_s[tid] = dt;
            dA_s[tid] = expf(dt * Aneg_s[tid]);
        }

        const int s0 = (t + 5) & 7, s1 = (t + 6) & 7, s2 = (t + 7) & 7, s3 = slot;
        float xv = cb;
        xv = fmaf(ring[s0][tid], w0, xv);
        xv = fmaf(ring[s1][tid], w1, xv);
        xv = fmaf(ring[s2][tid], w2, xv);
        xv = fmaf(ring[s3][tid], w3, xv);
        xv = xv / (1.f + expf(-xv));
        if (tid < 128) {
            float v = cb2;
            v = fmaf(ring[s0][c2], u0, v);
            v = fmaf(ring[s1][c2], u1, v);
            v = fmaf(ring[s2][c2], u2, v);
            v = fmaf(ring[s3][c2], u3, v);
            v = v / (1.f + expf(-v));
            if (tid < 64) Bsh[tid] = v; else Csh[tid - 64] = v;
        }
        __syncthreads();

        const float dA  = dA_s[head];
        const float dtx = dt_s[head] * xv;
        const ull dA2  = pack2(dA, dA);
        const ull dtx2 = pack2(dtx, dtx);
        ull y2 = pack2(0.f, 0.f);
        const ull* B2 = (const ull*)Bsh;
        const ull* C2 = (const ull*)Csh;
#pragma unroll
        for (int n = 0; n < 32; n++) {
            ull tb;
            MUL_X2(tb, dtx2, B2[n]);
            FMA_X2(h2[n], h2[n], dA2, tb);
            FMA_X2(y2, h2[n], C2[n], y2);
        }
        float ylo, yhi;
        asm("mov.b64 {%0, %1}, %2;" : "=f"(ylo), "=f"(yhi) : "l"(y2));
        float y = ylo + yhi;
        y = fmaf(xv, Dh, y);

        const float z = zbuf[t & 3][tid];
        float g = y * (z / (1.f + expf(-z)));
        float ss = g * g;
#pragma unroll
        for (int o = 16; o; o >>= 1) ss += __shfl_xor_sync(0xffffffffu, ss, o);
        if ((tid & 31) == 0) red[tid >> 5] = ss;
        __syncthreads();
        float v = red[tid & 15];
#pragma unroll
        for (int o = 8; o; o >>= 1) v += __shfl_xor_sync(0xffffffffu, v, o);
        float s_inv = rsqrtf(v * (1.0f / 512.0f) + 1e-5f);

        float val = g * s_inv * nw;
        __nv_bfloat16 hh = __float2bfloat16(val);
        size_t oidx = (size_t)(base + t * stride) * KFIN + ycol_off + tid;
        g_Yhi[oidx] = hh;
        g_Ylo[oidx] = __float2bfloat16(val - __bfloat162float(hh));
    }
}

// ---------------- fold fc_w into out_w -----------------------------------------
__global__ void __launch_bounds__(256) wcomb_kernel(
    const float* __restrict__ mh_out_w, const float* __restrict__ mv_out_w,
    const float* __restrict__ fc_w)
{
    const int d  = blockIdx.x;
    const int k0 = blockIdx.y * 64;
    const int nb = blockIdx.z * 32;
    const float* ow = d ? mh_out_w : mv_out_w;
    const int fo = d ? 512 : 0;
    __shared__ float ows[64][65];
    __shared__ float fs[32][65];
    const int kk = threadIdx.x & 63;
    const int ng = threadIdx.x >> 6;      // 0..3
    float acc[8];
#pragma unroll
    for (int i = 0; i < 8; i++) acc[i] = 0.f;

    for (int jo = 0; jo < 256; jo += 64) {
        for (int idx = threadIdx.x; idx < 64 * 64; idx += 256) {
            int j = idx >> 6, c = idx & 63;
            ows[j][c] = ow[(size_t)(jo + j) * 512 + k0 + c];
        }
        for (int idx = threadIdx.x; idx < 32 * 64; idx += 256) {
            int n = idx >> 6, jj = idx & 63;
            fs[n][jj] = fc_w[(size_t)(nb + n) * 1024 + fo + jo + jj] +
                        fc_w[(size_t)(nb + n) * 1024 + fo + 256 + jo + jj];
        }
        __syncthreads();
#pragma unroll 4
        for (int j = 0; j < 64; j++) {
            float o = ows[j][kk];
#pragma unroll
            for (int i = 0; i < 8; i++)
                acc[i] = fmaf(o, fs[ng * 8 + i][j], acc[i]);
        }
        __syncthreads();
    }
#pragma unroll
    for (int i = 0; i < 8; i++) {
        float val = acc[i];
        __nv_bfloat16 hh = __float2bfloat16(val);
        size_t idx = (size_t)(nb + ng * 8 + i) * KFIN + d * 512 + (k0 + kk);
        g_WcBhi[idx] = hh;
        g_WcBlo[idx] = __float2bfloat16(val - __bfloat162float(hh));
    }
}

// ---------------- launch ----------------
extern "C" void kernel_launch(void* const* d_in, const int* in_sizes, int n_in,
                              void* d_out, int out_size)
{
    (void)in_sizes; (void)n_in; (void)out_size;
    const float* x          = (const float*)d_in[0];
    const float* mh_in_w    = (const float*)d_in[1];
    const float* mh_conv_w  = (const float*)d_in[2];
    const float* mh_conv_b  = (const float*)d_in[3];
    const float* mh_dt_bias = (const float*)d_in[4];
    const float* mh_A_log   = (const float*)d_in[5];
    const float* mh_D       = (const float*)d_in[6];
    const float* mh_norm_w  = (const float*)d_in[7];
    const float* mh_out_w   = (const float*)d_in[8];
    const float* mv_in_w    = (const float*)d_in[9];
    const float* mv_conv_w  = (const float*)d_in[10];
    const float* mv_conv_b  = (const float*)d_in[11];
    const float* mv_dt_bias = (const float*)d_in[12];
    const float* mv_A_log   = (const float*)d_in[13];
    const float* mv_D       = (const float*)d_in[14];
    const float* mv_norm_w  = (const float*)d_in[15];
    const float* mv_out_w   = (const float*)d_in[16];
    const float* fc_w       = (const float*)d_in[17];
    const float* fc_b       = (const float*)d_in[18];
    float* out = (float*)d_out;

    float *Zh, *Zv;
    __nv_bfloat16 *Xhi, *Xlo, *Whhi, *Whlo, *Wvhi, *Wvlo, *Yhi, *Ylo, *WcBhi, *WcBlo;
    cudaGetSymbolAddress((void**)&Zh,   g_Zh);
    cudaGetSymbolAddress((void**)&Zv,   g_Zv);
    cudaGetSymbolAddress((void**)&Xhi,  g_Xhi);
    cudaGetSymbolAddress((void**)&Xlo,  g_Xlo);
    cudaGetSymbolAddress((void**)&Whhi, g_Whhi);
    cudaGetSymbolAddress((void**)&Whlo, g_Whlo);
    cudaGetSymbolAddress((void**)&Wvhi, g_Wvhi);
    cudaGetSymbolAddress((void**)&Wvlo, g_Wvlo);
    cudaGetSymbolAddress((void**)&Yhi,  g_Yhi);
    cudaGetSymbolAddress((void**)&Ylo,  g_Ylo);
    cudaGetSymbolAddress((void**)&WcBhi, g_WcBhi);
    cudaGetSymbolAddress((void**)&WcBlo, g_WcBlo);

    cudaFuncSetAttribute(gemm_mma, cudaFuncAttributeMaxDynamicSharedMemorySize, GSMEM);

    const dim3 g_in(NTOK / BM, NPAD1 / BN);     // (128, 10)
    const dim3 g_fin(NTOK / BM, D_MODEL / BN);  // (128, 2)

    cvt_x_kernel<<<NTOK * D_MODEL / 4 / 256, 256>>>(x);
    prep_w_kernel<<<(NPAD1 * D_MODEL + 255) / 256, 256>>>(mh_in_w, Whhi, Whlo);
    prep_w_kernel<<<(NPAD1 * D_MODEL + 255) / 256, 256>>>(mv_in_w, Wvhi, Wvlo);
    wcomb_kernel<<<dim3(2, 8, 8), 256>>>(mh_out_w, mv_out_w, fc_w);

    gemm_mma<<<g_in, 256, GSMEM>>>(Xhi, Xlo, Whhi, Whlo, Zh, D_MODEL, NPAD1, nullptr);
    gemm_mma<<<g_in, 256, GSMEM>>>(Xhi, Xlo, Wvhi, Wvlo, Zv, D_MODEL, NPAD1, nullptr);

    scan_kernel<<<NSEQ, 512>>>(Zh, mh_conv_w, mh_conv_b, mh_dt_bias, mh_A_log,
                               mh_D, mh_norm_w, 0, 512);
    scan_kernel<<<NSEQ, 512>>>(Zv, mv_conv_w, mv_conv_b, mv_dt_bias, mv_A_log,
                               mv_D, mv_norm_w, 1, 0);

    gemm_mma<<<g_fin, 256, GSMEM>>>(Yhi, Ylo, WcBhi, WcBlo, out, KFIN, D_MODEL, fc_b);
}

// round 6
// speedup vs baseline: 2.0698x; 1.0797x over previous
#include <cuda_runtime.h>
#include <cuda_bf16.h>
#include <math.h>
#include <stdint.h>

#define D_MODEL   256
#define D_INNER   512
#define CONV_CH   640
#define D_IN_PROJ 1160
#define NPAD1     1280
#define SEQ       64
#define NSEQ      512
#define NTOK      32768
#define KFIN      1024

// ---------------- scratch ------------------------------------------------------
__device__ float         g_Zh  [(size_t)NTOK * NPAD1];
__device__ float         g_Zv  [(size_t)NTOK * NPAD1];
__device__ __nv_bfloat16 g_Xhi [(size_t)NTOK * D_MODEL];
__device__ __nv_bfloat16 g_Xlo [(size_t)NTOK * D_MODEL];
__device__ __nv_bfloat16 g_Whhi[(size_t)NPAD1 * D_MODEL];
__device__ __nv_bfloat16 g_Whlo[(size_t)NPAD1 * D_MODEL];
__device__ __nv_bfloat16 g_Wvhi[(size_t)NPAD1 * D_MODEL];
__device__ __nv_bfloat16 g_Wvlo[(size_t)NPAD1 * D_MODEL];
__device__ __nv_bfloat16 g_Yhi [(size_t)NTOK * KFIN];
__device__ __nv_bfloat16 g_Ylo [(size_t)NTOK * KFIN];
__device__ __nv_bfloat16 g_WcBhi[(size_t)D_MODEL * KFIN];
__device__ __nv_bfloat16 g_WcBlo[(size_t)D_MODEL * KFIN];

// ---------------- helpers ------------------------------------------------------
__device__ __forceinline__ uint32_t smem_u32(const void* p) {
    uint32_t a;
    asm("{ .reg .u64 t; cvta.to.shared.u64 t, %1; cvt.u32.u64 %0, t; }" : "=r"(a) : "l"(p));
    return a;
}
__device__ __forceinline__ uint32_t sw64(uint32_t off) {   // 64B-row swizzle
    return off ^ ((off >> 3) & 0x30);
}
#define CP16(dst, src) \
    asm volatile("cp.async.cg.shared.global [%0], [%1], 16;" :: "r"(dst), "l"(src))
#define CP_COMMIT() asm volatile("cp.async.commit_group;" ::: "memory")
#define CP_WAIT(n)  asm volatile("cp.async.wait_group %0;" :: "n"(n) : "memory")

typedef unsigned long long ull;
__device__ __forceinline__ ull pack2(float lo, float hi) {
    ull r; asm("mov.b64 %0, {%1, %2};" : "=l"(r) : "f"(lo), "f"(hi)); return r;
}
#define FMA_X2(d, a, b, c) \
    asm("fma.rn.f32x2 %0, %1, %2, %3;" : "=l"(d) : "l"(a), "l"(b), "l"(c))
#define MUL_X2(d, a, b) \
    asm("mul.rn.f32x2 %0, %1, %2;" : "=l"(d) : "l"(a), "l"(b))

// ---------------- conversion kernels -------------------------------------------
__global__ void cvt_x_kernel(const float* __restrict__ in) {
    size_t i = (size_t)blockIdx.x * 256 + threadIdx.x;
    float4 v = ((const float4*)in)[i];
    __nv_bfloat16 h0 = __float2bfloat16(v.x), h1 = __float2bfloat16(v.y);
    __nv_bfloat16 h2 = __float2bfloat16(v.z), h3 = __float2bfloat16(v.w);
    __nv_bfloat162 hi01; hi01.x = h0; hi01.y = h1;
    __nv_bfloat162 hi23; hi23.x = h2; hi23.y = h3;
    __nv_bfloat162 lo01, lo23;
    lo01.x = __float2bfloat16(v.x - __bfloat162float(h0));
    lo01.y = __float2bfloat16(v.y - __bfloat162float(h1));
    lo23.x = __float2bfloat16(v.z - __bfloat162float(h2));
    lo23.y = __float2bfloat16(v.w - __bfloat162float(h3));
    ((__nv_bfloat162*)g_Xhi)[2 * i]     = hi01;
    ((__nv_bfloat162*)g_Xhi)[2 * i + 1] = hi23;
    ((__nv_bfloat162*)g_Xlo)[2 * i]     = lo01;
    ((__nv_bfloat162*)g_Xlo)[2 * i + 1] = lo23;
}

__global__ void prep_w_kernel(const float* __restrict__ wh, const float* __restrict__ wv) {
    int i = blockIdx.x * 256 + threadIdx.x;
    const float* w = blockIdx.y ? wv : wh;
    __nv_bfloat16* whi = blockIdx.y ? g_Wvhi : g_Whhi;
    __nv_bfloat16* wlo = blockIdx.y ? g_Wvlo : g_Whlo;
    if (i < NPAD1 * D_MODEL) {
        int n = i >> 8;
        float v = (n < D_IN_PROJ) ? w[i] : 0.f;
        __nv_bfloat16 h = __float2bfloat16(v);
        whi[i] = h;
        wlo[i] = __float2bfloat16(v - __bfloat162float(h));
    }
}

// ---------------- mma.sync split-bf16 GEMM --------------------------------------
// C = Ahi*Bhi + Ahi*Blo + Alo*Bhi, single K pass. A:[M][K], B:[N][K] k-major.
// Tile 128x128, 8 warps (2x4), warp 64x32, BK=32, 3-stage ring, 2 CTAs/SM.
#define BMg 128
#define BNg 128
#define TILE_Bg  8192            // 128x32 bf16
#define STAGE_Bg 32768           // 4 tiles
#define GSMEM    (3 * STAGE_Bg)  // 98304

__global__ void __launch_bounds__(256, 2) gemm_mma(
    const __nv_bfloat16* __restrict__ Ahi, const __nv_bfloat16* __restrict__ Alo,
    const __nv_bfloat16* __restrict__ B0hi, const __nv_bfloat16* __restrict__ B0lo,
    const __nv_bfloat16* __restrict__ B1hi, const __nv_bfloat16* __restrict__ B1lo,
    float* __restrict__ C0, float* __restrict__ C1,
    int K, int ldc, const float* __restrict__ bias)
{
    extern __shared__ __nv_bfloat16 sm[];
    const uint32_t smb = smem_u32(sm);
    const int tid = threadIdx.x, lane = tid & 31, wid = tid >> 5;
    const int m0 = blockIdx.x * BMg, n0 = blockIdx.y * BNg;
    const int wm = (wid & 1) * 64, wn = 32 * (wid >> 1);
    const int nk = K >> 5;

    const __nv_bfloat16* Bhi = blockIdx.z ? B1hi : B0hi;
    const __nv_bfloat16* Blo = blockIdx.z ? B1lo : B0lo;
    float* C = blockIdx.z ? C1 : C0;

    uint32_t arow[4], brow[2];
#pragma unroll
    for (int mt = 0; mt < 4; mt++)
        arow[mt] = (uint32_t)(wm + mt * 16 + (lane & 15)) * 64 + (lane >> 4) * 16;
#pragma unroll
    for (int nb = 0; nb < 2; nb++)
        brow[nb] = (uint32_t)(wn + nb * 16 + (lane & 15)) * 64 + (lane >> 4) * 16;

    float acc[4][4][4];
#pragma unroll
    for (int a = 0; a < 4; a++)
#pragma unroll
        for (int b = 0; b < 4; b++)
#pragma unroll
            for (int c = 0; c < 4; c++) acc[a][b][c] = 0.f;

    const int lrow = tid & 127, half = tid >> 7;
    const uint32_t rb = (uint32_t)lrow * 64 + half * 32;

    auto load_stage = [&](int s, int c) {
        const int koff = c * 32 + half * 16;
        const uint32_t base = smb + s * STAGE_Bg;
        const __nv_bfloat16* pAhi = Ahi + (size_t)(m0 + lrow) * K + koff;
        const __nv_bfloat16* pAlo = Alo + (size_t)(m0 + lrow) * K + koff;
        const __nv_bfloat16* pBhi = Bhi + (size_t)(n0 + lrow) * K + koff;
        const __nv_bfloat16* pBlo = Blo + (size_t)(n0 + lrow) * K + koff;
#pragma unroll
        for (int ch = 0; ch < 2; ch++) {
            uint32_t d = sw64(rb + ch * 16);
            CP16(base + d, pAhi + ch * 8);
            CP16(base + TILE_Bg + d, pAlo + ch * 8);
            CP16(base + 2 * TILE_Bg + d, pBhi + ch * 8);
            CP16(base + 3 * TILE_Bg + d, pBlo + ch * 8);
        }
        CP_COMMIT();
    };

    load_stage(0, 0);
    load_stage(1, 1);

    for (int c = 0; c < nk; c++) {
        if (c + 1 < nk) CP_WAIT(1); else CP_WAIT(0);
        __syncthreads();
        if (c + 2 < nk) load_stage((c + 2) % 3, c + 2);

        const uint32_t base = smb + (c % 3) * STAGE_Bg;
        const uint32_t aHiB = base, aLoB = base + TILE_Bg;
        const uint32_t bHiB = base + 2 * TILE_Bg, bLoB = base + 3 * TILE_Bg;
#pragma unroll
        for (int ks = 0; ks < 2; ks++) {
            uint32_t ahi[4][4], alo[4][4], bhi[2][4], blo[2][4];
#pragma unroll
            for (int mt = 0; mt < 4; mt++) {
                uint32_t sw = sw64(arow[mt] + ks * 32);
                asm volatile("ldmatrix.sync.aligned.m8n8.x4.shared.b16 {%0,%1,%2,%3}, [%4];"
                             : "=r"(ahi[mt][0]), "=r"(ahi[mt][1]), "=r"(ahi[mt][2]), "=r"(ahi[mt][3])
                             : "r"(aHiB + sw));
                asm volatile("ldmatrix.sync.aligned.m8n8.x4.shared.b16 {%0,%1,%2,%3}, [%4];"
                             : "=r"(alo[mt][0]), "=r"(alo[mt][1]), "=r"(alo[mt][2]), "=r"(alo[mt][3])
                             : "r"(aLoB + sw));
            }
#pragma unroll
            for (int nb = 0; nb < 2; nb++) {
                uint32_t sw = sw64(brow[nb] + ks * 32);
                asm volatile("ldmatrix.sync.aligned.m8n8.x4.shared.b16 {%0,%1,%2,%3}, [%4];"
                             : "=r"(bhi[nb][0]), "=r"(bhi[nb][1]), "=r"(bhi[nb][2]), "=r"(bhi[nb][3])
                             : "r"(bHiB + sw));
                asm volatile("ldmatrix.sync.aligned.m8n8.x4.shared.b16 {%0,%1,%2,%3}, [%4];"
                             : "=r"(blo[nb][0]), "=r"(blo[nb][1]), "=r"(blo[nb][2]), "=r"(blo[nb][3])
                             : "r"(bLoB + sw));
            }
#define MMA_PASS(AF, BF)                                                              \
            _Pragma("unroll")                                                         \
            for (int mt = 0; mt < 4; mt++)                                            \
                _Pragma("unroll")                                                     \
                for (int nb = 0; nb < 2; nb++) {                                      \
                    asm volatile(                                                     \
                        "mma.sync.aligned.m16n8k16.row.col.f32.bf16.bf16.f32 "        \
                        "{%0,%1,%2,%3}, {%4,%5,%6,%7}, {%8,%9}, {%0,%1,%2,%3};"       \
                        : "+f"(acc[mt][nb * 2][0]), "+f"(acc[mt][nb * 2][1]),         \
                          "+f"(acc[mt][nb * 2][2]), "+f"(acc[mt][nb * 2][3])          \
                        : "r"(AF[mt][0]), "r"(AF[mt][1]), "r"(AF[mt][2]), "r"(AF[mt][3]), \
                          "r"(BF[nb][0]), "r"(BF[nb][2]));                            \
                    asm volatile(                                                     \
                        "mma.sync.aligned.m16n8k16.row.col.f32.bf16.bf16.f32 "        \
                        "{%0,%1,%2,%3}, {%4,%5,%6,%7}, {%8,%9}, {%0,%1,%2,%3};"       \
                        : "+f"(acc[mt][nb * 2 + 1][0]), "+f"(acc[mt][nb * 2 + 1][1]), \
                          "+f"(acc[mt][nb * 2 + 1][2]), "+f"(acc[mt][nb * 2 + 1][3])  \
                        : "r"(AF[mt][0]), "r"(AF[mt][1]), "r"(AF[mt][2]), "r"(AF[mt][3]), \
                          "r"(BF[nb][1]), "r"(BF[nb][3]));                            \
                }
            MMA_PASS(ahi, bhi)
            MMA_PASS(ahi, blo)
            MMA_PASS(alo, bhi)
#undef MMA_PASS
        }
    }

#pragma unroll
    for (int mt = 0; mt < 4; mt++) {
        int row = m0 + wm + mt * 16 + (lane >> 2);
#pragma unroll
        for (int nt = 0; nt < 4; nt++) {
            int col = n0 + wn + nt * 8 + (lane & 3) * 2;
            float2 v0 = make_float2(acc[mt][nt][0], acc[mt][nt][1]);
            float2 v1 = make_float2(acc[mt][nt][2], acc[mt][nt][3]);
            if (bias) {
                float b0 = bias[col], b1 = bias[col + 1];
                v0.x += b0; v0.y += b1; v1.x += b0; v1.y += b1;
            }
            *(float2*)&C[(size_t)row * ldc + col] = v0;
            *(float2*)&C[(size_t)(row + 8) * ldc + col] = v1;
        }
    }
}

// ---------------- fused conv + SiLU + softplus + SSM scan + gate + RMSnorm ------
// Merged: 1024 blocks; block >> 9 selects direction (0 = h, 1 = v).
__global__ void __launch_bounds__(512, 1) scan_kernel(
    const float* __restrict__ cwh, const float* __restrict__ cbh,
    const float* __restrict__ dtbh, const float* __restrict__ Alh,
    const float* __restrict__ Dh_, const float* __restrict__ nwh,
    const float* __restrict__ cwv, const float* __restrict__ cbv,
    const float* __restrict__ dtbv, const float* __restrict__ Alv,
    const float* __restrict__ Dv_, const float* __restrict__ nwv)
{
    const int tid  = threadIdx.x;
    const int head = tid >> 6;
    const int dir  = blockIdx.x >> 9;       // 0 = h, 1 = v
    const int s    = blockIdx.x & 511;

    const float* Z       = dir ? g_Zv : g_Zh;
    const float* conv_w  = dir ? cwv : cwh;
    const float* conv_b  = dir ? cbv : cbh;
    const float* dt_bias = dir ? dtbv : dtbh;
    const float* A_log   = dir ? Alv : Alh;
    const float* Dvv     = dir ? Dv_ : Dh_;
    const float* norm_w  = dir ? nwv : nwh;
    const int ycol_off   = dir ? 0 : 512;

    int base, stride;
    if (dir) { int b = s >> 6, w = s & 63; base = b * 4096 + w; stride = 64; }
    else     { base = s * 64; stride = 1; }

    __shared__ __align__(16) float ring[8][CONV_CH];
    __shared__ __align__(16) float zbuf[4][512];
    __shared__ __align__(16) float dtbuf[4][8];
    __shared__ __align__(16) float Bsh[64];
    __shared__ __align__(16) float Csh[64];
    __shared__ float dt_s[8], dA_s[8], Aneg_s[8], dtb_s[8];
    __shared__ float red[16];

    for (int i = tid; i < 8 * CONV_CH; i += 512) (&ring[0][0])[i] = 0.f;
    if (tid < 8) { Aneg_s[tid] = -expf(A_log[tid]); dtb_s[tid] = dt_bias[tid]; }

    const float w0 = conv_w[tid * 4 + 0], w1 = conv_w[tid * 4 + 1];
    const float w2 = conv_w[tid * 4 + 2], w3 = conv_w[tid * 4 + 3];
    const float cb = conv_b[tid];
    float u0 = 0.f, u1 = 0.f, u2 = 0.f, u3 = 0.f, cb2 = 0.f;
    const int c2 = 512 + tid;
    if (tid < 128) {
        u0 = conv_w[c2 * 4 + 0]; u1 = conv_w[c2 * 4 + 1];
        u2 = conv_w[c2 * 4 + 2]; u3 = conv_w[c2 * 4 + 3];
        cb2 = conv_b[c2];
    }
    const float Dhv = Dvv[head];
    const float nw = norm_w[tid];

    ull h2[32];
#pragma unroll
    for (int n = 0; n < 32; n++) h2[n] = pack2(0.f, 0.f);

    const uint32_t ring_b = smem_u32(&ring[0][0]);
    const uint32_t zbuf_b = smem_u32(&zbuf[0][0]);
    const uint32_t dtb_b  = smem_u32(&dtbuf[0][0]);

    auto prefetch = [&](int tt) {
        if (tt < SEQ) {
            const float* row = Z + (size_t)(base + tt * stride) * NPAD1;
            if (tid < 160)       CP16(ring_b + (tt & 7) * (CONV_CH * 4) + tid * 16, row + 512 + tid * 4);
            else if (tid < 288)  CP16(zbuf_b + (tt & 3) * 2048 + (tid - 160) * 16, row + (tid - 160) * 4);
            else if (tid < 290)  CP16(dtb_b + (tt & 3) * 32 + (tid - 288) * 16, row + 1152 + (tid - 288) * 4);
        }
        CP_COMMIT();
    };

    __syncthreads();
    prefetch(0);
    prefetch(1);

    for (int t = 0; t < SEQ; t++) {
        if (t < SEQ - 1) CP_WAIT(1); else CP_WAIT(0);
        __syncthreads();
        prefetch(t + 2);

        const int slot = t & 7;
        if (tid < 8) {
            float draw = dtbuf[t & 3][tid] + dtb_s[tid];
            float dt = (draw > 20.f) ? draw : log1pf(expf(draw));
            dt_s[tid] = dt;
            dA_s[tid] = expf(dt * Aneg_s[tid]);
        }

        const int s0 = (t + 5) & 7, s1 = (t + 6) & 7, s2 = (t + 7) & 7, s3 = slot;
        float xv = cb;
        xv = fmaf(ring[s0][tid], w0, xv);
        xv = fmaf(ring[s1][tid], w1, xv);
        xv = fmaf(ring[s2][tid], w2, xv);
        xv = fmaf(ring[s3][tid], w3, xv);
        xv = xv / (1.f + expf(-xv));
        if (tid < 128) {
            float v = cb2;
            v = fmaf(ring[s0][c2], u0, v);
            v = fmaf(ring[s1][c2], u1, v);
            v = fmaf(ring[s2][c2], u2, v);
            v = fmaf(ring[s3][c2], u3, v);
            v = v / (1.f + expf(-v));
            if (tid < 64) Bsh[tid] = v; else Csh[tid - 64] = v;
        }
        __syncthreads();

        const float dA  = dA_s[head];
        const float dtx = dt_s[head] * xv;
        const ull dA2  = pack2(dA, dA);
        const ull dtx2 = pack2(dtx, dtx);
        ull y2 = pack2(0.f, 0.f);
        const ull* B2 = (const ull*)Bsh;
        const ull* C2 = (const ull*)Csh;
#pragma unroll
        for (int n = 0; n < 32; n++) {
            ull tb;
            MUL_X2(tb, dtx2, B2[n]);
            FMA_X2(h2[n], h2[n], dA2, tb);
            FMA_X2(y2, h2[n], C2[n], y2);
        }
        float ylo, yhi;
        asm("mov.b64 {%0, %1}, %2;" : "=f"(ylo), "=f"(yhi) : "l"(y2));
        float y = ylo + yhi;
        y = fmaf(xv, Dhv, y);

        const float z = zbuf[t & 3][tid];
        float g = y * (z / (1.f + expf(-z)));
        float ss = g * g;
#pragma unroll
        for (int o = 16; o; o >>= 1) ss += __shfl_xor_sync(0xffffffffu, ss, o);
        if ((tid & 31) == 0) red[tid >> 5] = ss;
        __syncthreads();
        float v = red[tid & 15];
#pragma unroll
        for (int o = 8; o; o >>= 1) v += __shfl_xor_sync(0xffffffffu, v, o);
        float s_inv = rsqrtf(v * (1.0f / 512.0f) + 1e-5f);

        float val = g * s_inv * nw;
        __nv_bfloat16 hh = __float2bfloat16(val);
        size_t oidx = (size_t)(base + t * stride) * KFIN + ycol_off + tid;
        g_Yhi[oidx] = hh;
        g_Ylo[oidx] = __float2bfloat16(val - __bfloat162float(hh));
    }
}

// ---------------- fold fc_w into out_w -----------------------------------------
__global__ void __launch_bounds__(256) wcomb_kernel(
    const float* __restrict__ mh_out_w, const float* __restrict__ mv_out_w,
    const float* __restrict__ fc_w)
{
    const int d  = blockIdx.x;
    const int k0 = blockIdx.y * 64;
    const int nb = blockIdx.z * 32;
    const float* ow = d ? mh_out_w : mv_out_w;
    const int fo = d ? 512 : 0;
    __shared__ float ows[64][65];
    __shared__ float fs[32][65];
    const int kk = threadIdx.x & 63;
    const int ng = threadIdx.x >> 6;
    float acc[8];
#pragma unroll
    for (int i = 0; i < 8; i++) acc[i] = 0.f;

    for (int jo = 0; jo < 256; jo += 64) {
        for (int idx = threadIdx.x; idx < 64 * 64; idx += 256) {
            int j = idx >> 6, c = idx & 63;
            ows[j][c] = ow[(size_t)(jo + j) * 512 + k0 + c];
        }
        for (int idx = threadIdx.x; idx < 32 * 64; idx += 256) {
            int n = idx >> 6, jj = idx & 63;
            fs[n][jj] = fc_w[(size_t)(nb + n) * 1024 + fo + jo + jj] +
                        fc_w[(size_t)(nb + n) * 1024 + fo + 256 + jo + jj];
        }
        __syncthreads();
#pragma unroll 4
        for (int j = 0; j < 64; j++) {
            float o = ows[j][kk];
#pragma unroll
            for (int i = 0; i < 8; i++)
                acc[i] = fmaf(o, fs[ng * 8 + i][j], acc[i]);
        }
        __syncthreads();
    }
#pragma unroll
    for (int i = 0; i < 8; i++) {
        float val = acc[i];
        __nv_bfloat16 hh = __float2bfloat16(val);
        size_t idx = (size_t)(nb + ng * 8 + i) * KFIN + d * 512 + (k0 + kk);
        g_WcBhi[idx] = hh;
        g_WcBlo[idx] = __float2bfloat16(val - __bfloat162float(hh));
    }
}

// ---------------- launch ----------------
extern "C" void kernel_launch(void* const* d_in, const int* in_sizes, int n_in,
                              void* d_out, int out_size)
{
    (void)in_sizes; (void)n_in; (void)out_size;
    const float* x          = (const float*)d_in[0];
    const float* mh_in_w    = (const float*)d_in[1];
    const float* mh_conv_w  = (const float*)d_in[2];
    const float* mh_conv_b  = (const float*)d_in[3];
    const float* mh_dt_bias = (const float*)d_in[4];
    const float* mh_A_log   = (const float*)d_in[5];
    const float* mh_D       = (const float*)d_in[6];
    const float* mh_norm_w  = (const float*)d_in[7];
    const float* mh_out_w   = (const float*)d_in[8];
    const float* mv_in_w    = (const float*)d_in[9];
    const float* mv_conv_w  = (const float*)d_in[10];
    const float* mv_conv_b  = (const float*)d_in[11];
    const float* mv_dt_bias = (const float*)d_in[12];
    const float* mv_A_log   = (const float*)d_in[13];
    const float* mv_D       = (const float*)d_in[14];
    const float* mv_norm_w  = (const float*)d_in[15];
    const float* mv_out_w   = (const float*)d_in[16];
    const float* fc_w       = (const float*)d_in[17];
    const float* fc_b       = (const float*)d_in[18];
    float* out = (float*)d_out;

    float *Zh, *Zv;
    __nv_bfloat16 *Xhi, *Xlo, *Whhi, *Whlo, *Wvhi, *Wvlo, *Yhi, *Ylo, *WcBhi, *WcBlo;
    cudaGetSymbolAddress((void**)&Zh,   g_Zh);
    cudaGetSymbolAddress((void**)&Zv,   g_Zv);
    cudaGetSymbolAddress((void**)&Xhi,  g_Xhi);
    cudaGetSymbolAddress((void**)&Xlo,  g_Xlo);
    cudaGetSymbolAddress((void**)&Whhi, g_Whhi);
    cudaGetSymbolAddress((void**)&Whlo, g_Whlo);
    cudaGetSymbolAddress((void**)&Wvhi, g_Wvhi);
    cudaGetSymbolAddress((void**)&Wvlo, g_Wvlo);
    cudaGetSymbolAddress((void**)&Yhi,  g_Yhi);
    cudaGetSymbolAddress((void**)&Ylo,  g_Ylo);
    cudaGetSymbolAddress((void**)&WcBhi, g_WcBhi);
    cudaGetSymbolAddress((void**)&WcBlo, g_WcBlo);

    cudaFuncSetAttribute(gemm_mma, cudaFuncAttributeMaxDynamicSharedMemorySize, GSMEM);

    cvt_x_kernel<<<NTOK * D_MODEL / 4 / 256, 256>>>(x);
    prep_w_kernel<<<dim3((NPAD1 * D_MODEL + 255) / 256, 2), 256>>>(mh_in_w, mv_in_w);
    wcomb_kernel<<<dim3(2, 8, 8), 256>>>(mh_out_w, mv_out_w, fc_w);

    // both in-proj GEMMs in one launch (z picks weight/output set)
    gemm_mma<<<dim3(NTOK / BMg, NPAD1 / BNg, 2), 256, GSMEM>>>(
        Xhi, Xlo, Whhi, Whlo, Wvhi, Wvlo, Zh, Zv, D_MODEL, NPAD1, nullptr);

    // both scans in one launch
    scan_kernel<<<2 * NSEQ, 512>>>(
        mh_conv_w, mh_conv_b, mh_dt_bias, mh_A_log, mh_D, mh_norm_w,
        mv_conv_w, mv_conv_b, mv_dt_bias, mv_A_log, mv_D, mv_norm_w);

    // final fused output GEMM
    gemm_mma<<<dim3(NTOK / BMg, D_MODEL / BNg, 1), 256, GSMEM>>>(
        Yhi, Ylo, WcBhi, WcBlo, WcBhi, WcBlo, out, out, KFIN, D_MODEL, fc_b);
}